// round 11
// baseline (speedup 1.0000x reference)
#include <cuda_runtime.h>
#include <cuda_fp16.h>
#include <math.h>

#define BB 4
#define NN 4096
#define CC 1024
#define HH 8
#define DD 128
#define M_TOT (BB*NN)      // 16384
#define KV_CHUNKS 8
#define KM_CHUNKS 64

#define NSTAGE     3

// qk/lepe big-tile GEMM smem: A [128][64h] + B [256][64h], row=144B
#define Q_A_B      (128 * 144)              // 18432
#define Q_B_B      (256 * 144)              // 36864
#define Q_STAGE_B  (Q_A_B + Q_B_B)          // 55296
#define Q_DSMEM    (NSTAGE * Q_STAGE_B)     // 165888

// out GEMM smem: two [128][64h] tiles (old layout)
#define H_TILE_B   (128 * 144)
#define H_STAGE_B  (2 * H_TILE_B)           // 36864
#define H_DSMEM    (NSTAGE * H_STAGE_B)     // 110592

// kv fp16 smem: two [32][128h] tiles, row = 272B
#define KVH_TILE_B  (32 * 272)
#define KVH_STAGE_B (2 * KVH_TILE_B)
#define KVH_DSMEM   (NSTAGE * KVH_STAGE_B)  // 52224

// ---------------- scratch ----------------
__device__ float  g_qk[(size_t)M_TOT * 2 * CC];
__device__ __half g_qrh[(size_t)M_TOT * CC];
__device__ __half g_krh[(size_t)M_TOT * CC];
__device__ __half g_lepeh[(size_t)M_TOT * CC];
__device__ float  g_kmean_part[KM_CHUNKS * BB * CC];
__device__ float  g_kmean[BB * CC];
__device__ float  g_z[BB * HH * NN];
__device__ float  g_kv_part[(size_t)KV_CHUNKS * BB * HH * DD * DD];
__device__ __half g_kvTh[(size_t)BB * HH * DD * DD];
__device__ __half g_xh[(size_t)M_TOT * CC];
__device__ __half g_qkwTh[(size_t)2 * CC * CC];
__device__ __half g_lepewTh[(size_t)3 * CC * CC];
__device__ float  g_theta[512];

// ---------------- helpers ----------------
__device__ __forceinline__ unsigned sptr(const void* p)
{
    return (unsigned)__cvta_generic_to_shared(p);
}
__device__ __forceinline__ void cp16(unsigned dst, const void* src)
{
    asm volatile("cp.async.cg.shared.global [%0], [%1], 16;" :: "r"(dst), "l"(src));
}
__device__ __forceinline__ void cp16z(unsigned dst, const void* src, int sz)
{
    asm volatile("cp.async.cg.shared.global [%0], [%1], 16, %2;" :: "r"(dst), "l"(src), "r"(sz));
}
#define CP_COMMIT() asm volatile("cp.async.commit_group;" ::: "memory")
#define CP_WAIT1()  asm volatile("cp.async.wait_group 1;" ::: "memory")

__device__ __forceinline__ void mma16(float c[4], unsigned a0, unsigned a1, unsigned a2,
                                      unsigned a3, unsigned b0, unsigned b1)
{
    asm volatile(
        "mma.sync.aligned.m16n8k16.row.col.f32.f16.f16.f32 "
        "{%0,%1,%2,%3},{%4,%5,%6,%7},{%8,%9},{%0,%1,%2,%3};"
        : "+f"(c[0]), "+f"(c[1]), "+f"(c[2]), "+f"(c[3])
        : "r"(a0), "r"(a1), "r"(a2), "r"(a3), "r"(b0), "r"(b1));
}

__device__ __forceinline__ void ldsm4t(unsigned r[4], unsigned addr)
{
    asm volatile("ldmatrix.sync.aligned.m8n8.x4.trans.shared.b16 {%0,%1,%2,%3}, [%4];"
                 : "=r"(r[0]), "=r"(r[1]), "=r"(r[2]), "=r"(r[3]) : "r"(addr));
}

// ---------------- prepasses ----------------
__global__ void cvt_half_kernel(const float* __restrict__ src, __half* __restrict__ dst)
{
    const size_t i = ((size_t)blockIdx.x * blockDim.x + threadIdx.x) * 8;
    float4 v0 = *(const float4*)(src + i);
    float4 v1 = *(const float4*)(src + i + 4);
    __half2 h0 = __floats2half2_rn(v0.x, v0.y);
    __half2 h1 = __floats2half2_rn(v0.z, v0.w);
    __half2 h2 = __floats2half2_rn(v1.x, v1.y);
    __half2 h3 = __floats2half2_rn(v1.z, v1.w);
    uint4 u;
    u.x = *(unsigned*)&h0; u.y = *(unsigned*)&h1;
    u.z = *(unsigned*)&h2; u.w = *(unsigned*)&h3;
    *(uint4*)(dst + i) = u;
}

__global__ void transpose_cvt_h_kernel(const float* __restrict__ src, __half* __restrict__ dst,
                                       int R, int C)
{
    __shared__ float t[32][33];
    const size_t plane = (size_t)blockIdx.z * R * C;
    const float* s = src + plane;
    __half* d = dst + plane;
    const int x = blockIdx.x * 32 + threadIdx.x;
    const int y0 = blockIdx.y * 32 + threadIdx.y;
#pragma unroll
    for (int j = 0; j < 32; j += 8)
        t[threadIdx.y + j][threadIdx.x] = s[(size_t)(y0 + j) * C + x];
    __syncthreads();
    const int ox = blockIdx.y * 32 + threadIdx.x;
    const int oy0 = blockIdx.x * 32 + threadIdx.y;
#pragma unroll
    for (int j = 0; j < 32; j += 8)
        d[(size_t)(oy0 + j) * R + ox] = __float2half_rn(t[threadIdx.x][threadIdx.y + j]);
}

__global__ void theta_init_kernel()
{
    const int k = threadIdx.x;
    g_theta[k] = (float)exp(-(double)k * (log(10000.0) / 512.0));
}

// ---------------- big-tile fp16 warp MMA: warp 64x64, K=64 tile ----------------
// A at lane base (wm*64+g)*144 + q*4 ; B at (wn*64+g)*144 + q*4 (within B region)
__device__ __forceinline__ void mma_tile_6464(const char* A, const char* B, float c[4][8][4])
{
#pragma unroll
    for (int ksi = 0; ksi < 4; ksi++) {
        unsigned a[4][4], b[8][2];
#pragma unroll
        for (int mt = 0; mt < 4; mt++) {
            const char* pa = A + mt * (16 * 144) + ksi * 32;
            a[mt][0] = *(const unsigned*)(pa);
            a[mt][1] = *(const unsigned*)(pa + 8 * 144);
            a[mt][2] = *(const unsigned*)(pa + 16);
            a[mt][3] = *(const unsigned*)(pa + 8 * 144 + 16);
        }
#pragma unroll
        for (int nt = 0; nt < 8; nt++) {
            const char* pb = B + nt * (8 * 144) + ksi * 32;
            b[nt][0] = *(const unsigned*)(pb);
            b[nt][1] = *(const unsigned*)(pb + 16);
        }
#pragma unroll
        for (int mt = 0; mt < 4; mt++)
#pragma unroll
            for (int nt = 0; nt < 8; nt++)
                mma16(c[mt][nt], a[mt][0], a[mt][1], a[mt][2], a[mt][3],
                      b[nt][0], b[nt][1]);
    }
}

// ---------------- qk GEMM (fp16, CTA 128x256) + fused bias/elu/rope ----------------
__global__ void __launch_bounds__(256, 1)
gemm_qk_f16(const float* __restrict__ bias)
{
    extern __shared__ __align__(16) char dsm[];
    const unsigned base = sptr(dsm);
    const int tid = threadIdx.x, lane = tid & 31, wid = tid >> 5;
    const int wm = wid >> 2, wn = wid & 3;
    const int br = blockIdx.y, bc = blockIdx.x;      // bc: 0..7 (256-col tiles)
    const __half* Ab = g_xh + (size_t)br * 128 * CC;
    const __half* Bw = g_qkwTh + (size_t)bc * 256 * CC;

    auto fill = [&](int kt, int st) {
        const int k0 = kt * 64;
        const unsigned Abase = base + st * Q_STAGE_B;
        const unsigned Bbase = Abase + Q_A_B;
#pragma unroll
        for (int i = 0; i < 4; i++) {          // A: 128 rows
            const int idx = tid + i * 256;
            const int r = idx >> 3, c8 = (idx & 7) * 8;
            cp16(Abase + r * 144 + c8 * 2, Ab + (size_t)r * CC + k0 + c8);
        }
#pragma unroll
        for (int i = 0; i < 8; i++) {          // B: 256 rows
            const int idx = tid + i * 256;
            const int r = idx >> 3, c8 = (idx & 7) * 8;
            cp16(Bbase + r * 144 + c8 * 2, Bw + (size_t)r * CC + k0 + c8);
        }
    };

    const int g = lane >> 2, q = lane & 3;
    const unsigned aoff = (wm * 64 + g) * 144 + q * 4;
    const unsigned boff = Q_A_B + (wn * 64 + g) * 144 + q * 4;

    float c[4][8][4] = {};
    fill(0, 0); CP_COMMIT();
    fill(1, 1); CP_COMMIT();
    for (int kt = 0; kt < 16; kt++) {
        const int st = kt % NSTAGE;
        CP_WAIT1();
        __syncthreads();
        if (kt + 2 < 16) fill(kt + 2, (kt + 2) % NSTAGE);
        CP_COMMIT();
        mma_tile_6464(dsm + st * Q_STAGE_B + aoff, dsm + st * Q_STAGE_B + boff, c);
    }

    const int t = lane & 3;
    const bool isq = (bc < 4);
    __half* rdst = isq ? g_qrh : g_krh;
#pragma unroll
    for (int nt = 0; nt < 8; nt++) {
        const int col = bc * 256 + wn * 64 + nt * 8 + 2 * t;
        const float b0 = bias[col], b1 = bias[col + 1];
        const int kp = (isq ? col : col - 1024) >> 1;
        const float theta = g_theta[kp];
#pragma unroll
        for (int mt = 0; mt < 4; mt++) {
#pragma unroll
            for (int e = 0; e < 2; e++) {
                const int row = br * 128 + wm * 64 + mt * 16 + g + e * 8;
                float v0 = c[mt][nt][2 * e]     + b0;
                float v1 = c[mt][nt][2 * e + 1] + b1;
                v0 = (v0 > 0.0f) ? (v0 + 1.0f) : expf(v0);
                v1 = (v1 > 0.0f) ? (v1 + 1.0f) : expf(v1);
                *(float2*)(g_qk + (size_t)row * 2048 + col) = make_float2(v0, v1);
                const int n = row & (NN - 1);
                float s, cw;
                sincosf((float)n * theta, &s, &cw);
                rdst[(size_t)row * 1024 + kp]       = __float2half_rn(cw * v0 - s * v1);
                rdst[(size_t)row * 1024 + 512 + kp] = __float2half_rn(cw * v1 + s * v0);
            }
        }
    }
}

// ---------------- lepe conv GEMM (fp16, CTA 128x256) -> g_lepeh ----------------
__global__ void __launch_bounds__(256, 1)
lepe_f16()
{
    extern __shared__ __align__(16) char dsm[];
    const unsigned base = sptr(dsm);
    const int tid = threadIdx.x, lane = tid & 31, wid = tid >> 5;
    const int wm = wid >> 2, wn = wid & 3;
    const int br = blockIdx.y, bc = blockIdx.x;      // bc: 0..3
    const int m0 = br * 128;

    auto fill = [&](int kt, int st) {
        const int tap = kt >> 4;
        const int k0 = (kt & 15) * 64;
        const __half* Bw = g_lepewTh + (size_t)tap * CC * CC + (size_t)bc * 256 * CC;
        const unsigned Abase = base + st * Q_STAGE_B;
        const unsigned Bbase = Abase + Q_A_B;
#pragma unroll
        for (int i = 0; i < 4; i++) {
            const int idx = tid + i * 256;
            const int r = idx >> 3, c8 = (idx & 7) * 8;
            const int m = m0 + r;
            int n = (m & (NN - 1)) + tap - 1;
            const int b = m >> 12;
            const bool valid = (n >= 0) && (n < NN);
            if (!valid) n = 0;
            cp16z(Abase + r * 144 + c8 * 2,
                  g_xh + ((size_t)(b * NN + n)) * CC + k0 + c8, valid ? 16 : 0);
        }
#pragma unroll
        for (int i = 0; i < 8; i++) {
            const int idx = tid + i * 256;
            const int r = idx >> 3, c8 = (idx & 7) * 8;
            cp16(Bbase + r * 144 + c8 * 2, Bw + (size_t)r * CC + k0 + c8);
        }
    };

    const int g = lane >> 2, q = lane & 3;
    const unsigned aoff = (wm * 64 + g) * 144 + q * 4;
    const unsigned boff = Q_A_B + (wn * 64 + g) * 144 + q * 4;

    float c[4][8][4] = {};
    fill(0, 0); CP_COMMIT();
    fill(1, 1); CP_COMMIT();
    for (int kt = 0; kt < 48; kt++) {
        const int st = kt % NSTAGE;
        CP_WAIT1();
        __syncthreads();
        if (kt + 2 < 48) fill(kt + 2, (kt + 2) % NSTAGE);
        CP_COMMIT();
        mma_tile_6464(dsm + st * Q_STAGE_B + aoff, dsm + st * Q_STAGE_B + boff, c);
    }

    const int t = lane & 3;
#pragma unroll
    for (int mt = 0; mt < 4; mt++)
#pragma unroll
        for (int nt = 0; nt < 8; nt++) {
            const int col = bc * 256 + wn * 64 + nt * 8 + 2 * t;
#pragma unroll
            for (int e = 0; e < 2; e++) {
                const int row = m0 + wm * 64 + mt * 16 + g + e * 8;
                *(__half2*)(g_lepeh + (size_t)row * CC + col) =
                    __floats2half2_rn(c[mt][nt][2 * e], c[mt][nt][2 * e + 1]);
            }
        }
}

// ---------------- kv GEMM (fp16, trans-ldmatrix): kvT[e][d] ----------------
__global__ void __launch_bounds__(256, 2)
kv_f16()
{
    extern __shared__ __align__(16) char dsm[];
    const unsigned base = sptr(dsm);
    const int tid = threadIdx.x, lane = tid & 31, wid = tid >> 5;
    const int wm = wid >> 2, wn = wid & 3;
    const int chunk = blockIdx.x;
    const int bh = blockIdx.y;
    const int b = bh >> 3, h = bh & 7;
    const int n_base = chunk * (NN / KV_CHUNKS);
    const __half* Xs = g_xh  + ((size_t)b * NN) * CC + h * 128;
    const __half* Ks = g_krh + ((size_t)b * NN) * CC + h * 128;

    auto fill = [&](int kt, int st) {
        const int n0 = n_base + kt * 32;
        const unsigned Sbase = base + st * KVH_STAGE_B;
#pragma unroll
        for (int i = 0; i < 4; i++) {
            const int idx = tid + i * 256;
            const int tile = idx >> 9;
            const int j = idx & 511;
            const int r = j >> 4, ch = j & 15;
            const __half* src = (tile ? Ks : Xs) + (size_t)(n0 + r) * CC + ch * 8;
            cp16(Sbase + tile * KVH_TILE_B + r * 272 + ch * 16, src);
        }
    };

    const int L = lane;
    const unsigned a_row = (L & 7) + ((L >> 4) << 3);
    const unsigned a_colh = ((L >> 3) & 1) << 3;
    const unsigned b_row = (L & 7) + (((L >> 3) & 1) << 3);
    const unsigned b_colh = (L >> 4) << 3;

    float c[4][4][4] = {};
    fill(0, 0); CP_COMMIT();
    fill(1, 1); CP_COMMIT();
    const int NT = (NN / KV_CHUNKS) / 32;
    for (int kt = 0; kt < NT; kt++) {
        const int st = kt % NSTAGE;
        CP_WAIT1();
        __syncthreads();
        if (kt + 2 < NT) fill(kt + 2, (kt + 2) % NSTAGE);
        CP_COMMIT();
        const unsigned Xt = base + st * KVH_STAGE_B;
        const unsigned Kt = Xt + KVH_TILE_B;
#pragma unroll
        for (int ksi = 0; ksi < 2; ksi++) {
            const int k0 = ksi * 16;
            unsigned a[4][4], bb[2][4];
#pragma unroll
            for (int mt = 0; mt < 4; mt++)
                ldsm4t(a[mt], Xt + (k0 + a_row) * 272 + (wm * 64 + mt * 16 + a_colh) * 2);
#pragma unroll
            for (int ntp = 0; ntp < 2; ntp++)
                ldsm4t(bb[ntp], Kt + (k0 + b_row) * 272 + (wn * 32 + ntp * 16 + b_colh) * 2);
#pragma unroll
            for (int mt = 0; mt < 4; mt++)
#pragma unroll
                for (int ntp = 0; ntp < 2; ntp++) {
                    mma16(c[mt][2 * ntp],     a[mt][0], a[mt][1], a[mt][2], a[mt][3],
                          bb[ntp][0], bb[ntp][1]);
                    mma16(c[mt][2 * ntp + 1], a[mt][0], a[mt][1], a[mt][2], a[mt][3],
                          bb[ntp][2], bb[ntp][3]);
                }
        }
    }

    float* outp = g_kv_part + ((size_t)chunk * BB * HH + bh) * DD * DD;
    const int g = lane >> 2, t = lane & 3;
#pragma unroll
    for (int mt = 0; mt < 4; mt++)
#pragma unroll
        for (int nt = 0; nt < 4; nt++) {
            const int col = wn * 32 + nt * 8 + 2 * t;
#pragma unroll
            for (int e = 0; e < 2; e++) {
                const int row = wm * 64 + mt * 16 + g + e * 8;
                *(float2*)(outp + row * DD + col) =
                    make_float2(c[mt][nt][2 * e], c[mt][nt][2 * e + 1]);
            }
        }
}

__global__ void kv_reduce_kernel()
{
    const int i = blockIdx.x * 256 + threadIdx.x;
    if (i >= BB * HH * DD * DD) return;
    float s = 0.f;
    for (int ch = 0; ch < KV_CHUNKS; ch++)
        s += g_kv_part[(size_t)ch * BB * HH * DD * DD + i];
    g_kvTh[i] = __float2half_rn(s * (1.0f / 64.0f));
}

// ---------------- out = (qr @ kv) * z + lepe + lepe_b ----------------
__global__ void __launch_bounds__(256, 2)
out_f16(float* __restrict__ out, const float* __restrict__ lbias)
{
    extern __shared__ __align__(16) char dsm[];
    const unsigned base = sptr(dsm);
    const int tid = threadIdx.x, lane = tid & 31, wid = tid >> 5;
    const int wm = wid >> 2, wn = wid & 3;
    const int rt = blockIdx.x;
    const int bh = blockIdx.y;
    const int b = bh >> 3, h = bh & 7;
    const __half* Aq = g_qrh + (size_t)(b * NN + rt * 128) * CC + h * 128;
    const __half* Bk = g_kvTh + (size_t)bh * DD * DD;

    auto fill = [&](int kt, int st) {
        const int k0 = kt * 64;
        const unsigned Abase = base + st * H_STAGE_B;
        const unsigned Bbase = Abase + H_TILE_B;
#pragma unroll
        for (int i = 0; i < 4; i++) {
            const int idx = tid + i * 256;
            const int r = idx >> 3, c8 = (idx & 7) * 8;
            cp16(Abase + r * 144 + c8 * 2, Aq + (size_t)r * CC + k0 + c8);
            cp16(Bbase + r * 144 + c8 * 2, Bk + (size_t)r * DD + k0 + c8);
        }
    };

    const int g = lane >> 2, q = lane & 3;
    const unsigned aoff = (wm * 64 + g) * 144 + q * 4;
    const unsigned boff = H_TILE_B + (wn * 32 + g) * 144 + q * 4;

    float c[4][4][4] = {};
    fill(0, 0); CP_COMMIT();
    fill(1, 1); CP_COMMIT();
    for (int kt = 0; kt < 2; kt++) {
        const int st = kt % NSTAGE;
        CP_WAIT1();
        __syncthreads();
        CP_COMMIT();
#pragma unroll
        for (int ksi = 0; ksi < 4; ksi++) {
            unsigned a[4][4], b[4][2];
            const char* A = dsm + st * H_STAGE_B + aoff;
            const char* B = dsm + st * H_STAGE_B + boff;
#pragma unroll
            for (int mt = 0; mt < 4; mt++) {
                const char* pa = A + mt * (16 * 144) + ksi * 32;
                a[mt][0] = *(const unsigned*)(pa);
                a[mt][1] = *(const unsigned*)(pa + 8 * 144);
                a[mt][2] = *(const unsigned*)(pa + 16);
                a[mt][3] = *(const unsigned*)(pa + 8 * 144 + 16);
            }
#pragma unroll
            for (int nt = 0; nt < 4; nt++) {
                const char* pb = B + nt * (8 * 144) + ksi * 32;
                b[nt][0] = *(const unsigned*)(pb);
                b[nt][1] = *(const unsigned*)(pb + 16);
            }
#pragma unroll
            for (int mt = 0; mt < 4; mt++)
#pragma unroll
                for (int nt = 0; nt < 4; nt++)
                    mma16(c[mt][nt], a[mt][0], a[mt][1], a[mt][2], a[mt][3],
                          b[nt][0], b[nt][1]);
        }
    }

    const int t = lane & 3;
#pragma unroll
    for (int mt = 0; mt < 4; mt++)
#pragma unroll
        for (int e = 0; e < 2; e++) {
            const int n = rt * 128 + wm * 64 + mt * 16 + g + e * 8;
            const float zv = g_z[bh * NN + n];
            const size_t rowoff = ((size_t)(b * NN + n)) * CC + h * 128;
            float* orow = out + rowoff;
            const __half* lrow = g_lepeh + rowoff;
#pragma unroll
            for (int nt = 0; nt < 4; nt++) {
                const int col = wn * 32 + nt * 8 + 2 * t;
                const float2 lv = __half22float2(*(const __half2*)(lrow + col));
                const float lb0 = lbias[h * 128 + col];
                const float lb1 = lbias[h * 128 + col + 1];
                *(float2*)(orow + col) =
                    make_float2(c[mt][nt][2 * e] * zv + lv.x + lb0,
                                c[mt][nt][2 * e + 1] * zv + lv.y + lb1);
            }
        }
}

// ---------------- k mean / z ----------------
__global__ void kmean_part_kernel()
{
    const int chunk = blockIdx.x;
    const int b = blockIdx.y;
    const int c4 = threadIdx.x * 4;
    float4 s = make_float4(0.f, 0.f, 0.f, 0.f);
    for (int n = chunk * (NN / KM_CHUNKS); n < (chunk + 1) * (NN / KM_CHUNKS); n++) {
        const float4 v = *(const float4*)(g_qk + ((size_t)(b * NN + n)) * 2048 + 1024 + c4);
        s.x += v.x; s.y += v.y; s.z += v.z; s.w += v.w;
    }
    *(float4*)(&g_kmean_part[(chunk * BB + b) * CC + c4]) = s;
}

__global__ void kmean_fin_kernel()
{
    const int i = blockIdx.x * 256 + threadIdx.x;
    if (i >= BB * CC) return;
    float s = 0.f;
    for (int ch = 0; ch < KM_CHUNKS; ch++) s += g_kmean_part[ch * BB * CC + i];
    g_kmean[i] = s * (1.0f / NN);
}

__global__ void z_kernel()
{
    const int gw = (blockIdx.x * blockDim.x + threadIdx.x) >> 5;
    const int lane = threadIdx.x & 31;
    if (gw >= BB * HH * NN) return;
    const int n = gw & (NN - 1);
    const int h = (gw >> 12) & 7;
    const int b = gw >> 15;
    const float* qrow = g_qk + ((size_t)(b * NN + n)) * 2048 + h * 128;
    const float* km = g_kmean + b * CC + h * 128;
    const float4 qv = *(const float4*)(qrow + lane * 4);
    const float4 kv = *(const float4*)(km + lane * 4);
    float s = qv.x * kv.x + qv.y * kv.y + qv.z * kv.z + qv.w * kv.w;
#pragma unroll
    for (int o = 16; o; o >>= 1) s += __shfl_xor_sync(0xffffffffu, s, o);
    if (lane == 0) g_z[gw] = 1.0f / (s + 1e-6f);
}

// ---------------- launch ----------------
extern "C" void kernel_launch(void* const* d_in, const int* in_sizes, int n_in,
                              void* d_out, int out_size)
{
    const float* x      = (const float*)d_in[0];
    const float* qk_w   = (const float*)d_in[1];
    const float* qk_b   = (const float*)d_in[2];
    const float* lepe_w = (const float*)d_in[3];
    const float* lepe_b = (const float*)d_in[4];
    float* out = (float*)d_out;

    static cudaStream_t s1 = nullptr, s2 = nullptr;
    static cudaEvent_t evRoot = nullptr, evXh = nullptr, evQK = nullptr,
                       evZ = nullptr, evL = nullptr;
    static int init_done = 0;
    if (!init_done) {
        cudaFuncSetAttribute(gemm_qk_f16, cudaFuncAttributeMaxDynamicSharedMemorySize, Q_DSMEM);
        cudaFuncSetAttribute(lepe_f16,    cudaFuncAttributeMaxDynamicSharedMemorySize, Q_DSMEM);
        cudaFuncSetAttribute(kv_f16,      cudaFuncAttributeMaxDynamicSharedMemorySize, KVH_DSMEM);
        cudaFuncSetAttribute(out_f16,     cudaFuncAttributeMaxDynamicSharedMemorySize, H_DSMEM);
        cudaStreamCreateWithFlags(&s1, cudaStreamNonBlocking);
        cudaStreamCreateWithFlags(&s2, cudaStreamNonBlocking);
        cudaEventCreateWithFlags(&evRoot, cudaEventDisableTiming);
        cudaEventCreateWithFlags(&evXh, cudaEventDisableTiming);
        cudaEventCreateWithFlags(&evQK, cudaEventDisableTiming);
        cudaEventCreateWithFlags(&evZ, cudaEventDisableTiming);
        cudaEventCreateWithFlags(&evL, cudaEventDisableTiming);
        init_done = 1;
    }

    __half* d_xh;      cudaGetSymbolAddress((void**)&d_xh,      g_xh);
    __half* d_qkwTh;   cudaGetSymbolAddress((void**)&d_qkwTh,   g_qkwTh);
    __half* d_lepewTh; cudaGetSymbolAddress((void**)&d_lepewTh, g_lepewTh);

    cudaEventRecord(evRoot, 0);
    cudaStreamWaitEvent(s1, evRoot, 0);

    // s1: theta + lepe weight transpose, then lepe after x-half
    theta_init_kernel<<<1, 512, 0, s1>>>();
    transpose_cvt_h_kernel<<<dim3(32, 32, 3), dim3(32, 8), 0, s1>>>(lepe_w, d_lepewTh, CC, CC);

    // s0: fp16 x
    cvt_half_kernel<<<M_TOT * CC / 2048, 256>>>(x, d_xh);
    cudaEventRecord(evXh, 0);

    cudaStreamWaitEvent(s1, evXh, 0);
    lepe_f16<<<dim3(4, 128), 256, Q_DSMEM, s1>>>();
    cudaEventRecord(evL, s1);

    // s0: attention chain
    transpose_cvt_h_kernel<<<dim3(64, 32, 1), dim3(32, 8)>>>(qk_w, d_qkwTh, CC, 2 * CC);
    gemm_qk_f16<<<dim3(8, 128), 256, Q_DSMEM>>>(qk_b);
    cudaEventRecord(evQK, 0);

    // s2: kmean + z overlapping kv
    cudaStreamWaitEvent(s2, evQK, 0);
    kmean_part_kernel<<<dim3(KM_CHUNKS, BB), 256, 0, s2>>>();
    kmean_fin_kernel<<<16, 256, 0, s2>>>();
    z_kernel<<<(BB * HH * NN * 32) / 256, 256, 0, s2>>>();
    cudaEventRecord(evZ, s2);

    // s0: kv
    kv_f16<<<dim3(KV_CHUNKS, BB * HH), 256, KVH_DSMEM>>>();
    kv_reduce_kernel<<<(BB * HH * DD * DD) / 256, 256>>>();

    // join
    cudaStreamWaitEvent(0, evZ, 0);
    cudaStreamWaitEvent(0, evL, 0);
    out_f16<<<dim3(32, 32), 256, H_DSMEM>>>(out, lepe_b);
}

// round 12
// speedup vs baseline: 1.1544x; 1.1544x over previous
#include <cuda_runtime.h>
#include <cuda_fp16.h>
#include <math.h>

#define BB 4
#define NN 4096
#define CC 1024
#define HH 8
#define DD 128
#define M_TOT (BB*NN)      // 16384
#define KV_CHUNKS 8
#define KM_CHUNKS 64

// fp16 qk/lepe/out GEMM smem: two [128][64h +pad] tiles per stage, row=144B
#define H_TILE_B   (128 * 144)              // 18432
#define H_STAGE_B  (2 * H_TILE_B)           // 36864
#define NSTAGE     3
#define H_DSMEM    (NSTAGE * H_STAGE_B)     // 110592

// kv fp16 smem: two [32][128h] tiles, row = 272B
#define KVH_TILE_B  (32 * 272)
#define KVH_STAGE_B (2 * KVH_TILE_B)
#define KVH_DSMEM   (NSTAGE * KVH_STAGE_B)  // 52224

// ---------------- scratch ----------------
__device__ float  g_qk[(size_t)M_TOT * 2 * CC];
__device__ __half g_qrh[(size_t)M_TOT * CC];
__device__ __half g_krh[(size_t)M_TOT * CC];
__device__ __half g_lepeh[(size_t)M_TOT * CC];
__device__ float  g_kmean_part[KM_CHUNKS * BB * CC];
__device__ float  g_kmean[BB * CC];
__device__ float  g_z[BB * HH * NN];
__device__ float  g_kv_part[(size_t)KV_CHUNKS * BB * HH * DD * DD];
__device__ __half g_kvTh[(size_t)BB * HH * DD * DD];
__device__ __half g_xh[(size_t)M_TOT * CC];
__device__ __half g_qkwTh[(size_t)2 * CC * CC];
__device__ __half g_lepewTh[(size_t)3 * CC * CC];
__device__ float  g_theta[512];

// ---------------- helpers ----------------
__device__ __forceinline__ unsigned sptr(const void* p)
{
    return (unsigned)__cvta_generic_to_shared(p);
}
__device__ __forceinline__ void cp16(unsigned dst, const void* src)
{
    asm volatile("cp.async.cg.shared.global [%0], [%1], 16;" :: "r"(dst), "l"(src));
}
__device__ __forceinline__ void cp16z(unsigned dst, const void* src, int sz)
{
    asm volatile("cp.async.cg.shared.global [%0], [%1], 16, %2;" :: "r"(dst), "l"(src), "r"(sz));
}
#define CP_COMMIT() asm volatile("cp.async.commit_group;" ::: "memory")
#define CP_WAIT1()  asm volatile("cp.async.wait_group 1;" ::: "memory")

__device__ __forceinline__ void mma16(float c[4], unsigned a0, unsigned a1, unsigned a2,
                                      unsigned a3, unsigned b0, unsigned b1)
{
    asm volatile(
        "mma.sync.aligned.m16n8k16.row.col.f32.f16.f16.f32 "
        "{%0,%1,%2,%3},{%4,%5,%6,%7},{%8,%9},{%0,%1,%2,%3};"
        : "+f"(c[0]), "+f"(c[1]), "+f"(c[2]), "+f"(c[3])
        : "r"(a0), "r"(a1), "r"(a2), "r"(a3), "r"(b0), "r"(b1));
}

__device__ __forceinline__ void ldsm4(unsigned r[4], unsigned addr)
{
    asm volatile("ldmatrix.sync.aligned.m8n8.x4.shared.b16 {%0,%1,%2,%3}, [%4];"
                 : "=r"(r[0]), "=r"(r[1]), "=r"(r[2]), "=r"(r[3]) : "r"(addr));
}
__device__ __forceinline__ void ldsm4t(unsigned r[4], unsigned addr)
{
    asm volatile("ldmatrix.sync.aligned.m8n8.x4.trans.shared.b16 {%0,%1,%2,%3}, [%4];"
                 : "=r"(r[0]), "=r"(r[1]), "=r"(r[2]), "=r"(r[3]) : "r"(addr));
}

// ---------------- prepasses ----------------
__global__ void cvt_half_kernel(const float* __restrict__ src, __half* __restrict__ dst)
{
    const size_t i = ((size_t)blockIdx.x * blockDim.x + threadIdx.x) * 8;
    float4 v0 = *(const float4*)(src + i);
    float4 v1 = *(const float4*)(src + i + 4);
    __half2 h0 = __floats2half2_rn(v0.x, v0.y);
    __half2 h1 = __floats2half2_rn(v0.z, v0.w);
    __half2 h2 = __floats2half2_rn(v1.x, v1.y);
    __half2 h3 = __floats2half2_rn(v1.z, v1.w);
    uint4 u;
    u.x = *(unsigned*)&h0; u.y = *(unsigned*)&h1;
    u.z = *(unsigned*)&h2; u.w = *(unsigned*)&h3;
    *(uint4*)(dst + i) = u;
}

__global__ void transpose_cvt_h_kernel(const float* __restrict__ src, __half* __restrict__ dst,
                                       int R, int C)
{
    __shared__ float t[32][33];
    const size_t plane = (size_t)blockIdx.z * R * C;
    const float* s = src + plane;
    __half* d = dst + plane;
    const int x = blockIdx.x * 32 + threadIdx.x;
    const int y0 = blockIdx.y * 32 + threadIdx.y;
#pragma unroll
    for (int j = 0; j < 32; j += 8)
        t[threadIdx.y + j][threadIdx.x] = s[(size_t)(y0 + j) * C + x];
    __syncthreads();
    const int ox = blockIdx.y * 32 + threadIdx.x;
    const int oy0 = blockIdx.x * 32 + threadIdx.y;
#pragma unroll
    for (int j = 0; j < 32; j += 8)
        d[(size_t)(oy0 + j) * R + ox] = __float2half_rn(t[threadIdx.x][threadIdx.y + j]);
}

__global__ void theta_init_kernel()
{
    const int k = threadIdx.x;
    g_theta[k] = (float)exp(-(double)k * (log(10000.0) / 512.0));
}

// ---------------- fp16 warp-tile MMA over K=64 tile (ldmatrix fragments) ----------------
// A/B are smem uint32 addresses incl. lane offsets:
//   A = Abase + (wm*64 + (lane&15))*144 + (lane>>4)*16
//   B = Bbase + (wn*32 + (lane&15))*144 + (lane>>4)*16
__device__ __forceinline__ void mma_tile_f16(unsigned A, unsigned B, float c[4][4][4])
{
#pragma unroll
    for (int ksi = 0; ksi < 4; ksi++) {
        unsigned a[4][4], bb[2][4];
#pragma unroll
        for (int mt = 0; mt < 4; mt++)
            ldsm4(a[mt], A + mt * 2304 + ksi * 32);           // 16*144 = 2304
#pragma unroll
        for (int ntp = 0; ntp < 2; ntp++)
            ldsm4(bb[ntp], B + ntp * 2304 + ksi * 32);
#pragma unroll
        for (int mt = 0; mt < 4; mt++)
#pragma unroll
            for (int ntp = 0; ntp < 2; ntp++) {
                mma16(c[mt][2 * ntp],     a[mt][0], a[mt][1], a[mt][2], a[mt][3],
                      bb[ntp][0], bb[ntp][2]);
                mma16(c[mt][2 * ntp + 1], a[mt][0], a[mt][1], a[mt][2], a[mt][3],
                      bb[ntp][1], bb[ntp][3]);
            }
    }
}

// ---------------- qk GEMM (fp16, K-tile 64) + fused bias/elu/rope ----------------
__global__ void __launch_bounds__(256, 2)
gemm_qk_f16(const float* __restrict__ bias)
{
    extern __shared__ __align__(16) char dsm[];
    const unsigned base = sptr(dsm);
    const int tid = threadIdx.x, lane = tid & 31, wid = tid >> 5;
    const int wm = wid >> 2, wn = wid & 3;
    const int br = blockIdx.y, bc = blockIdx.x;
    const __half* Ab = g_xh + (size_t)br * 128 * CC;
    const __half* Bw = g_qkwTh + (size_t)bc * 128 * CC;

    auto fill = [&](int kt, int st) {
        const int k0 = kt * 64;
        const unsigned Abase = base + st * H_STAGE_B;
        const unsigned Bbase = Abase + H_TILE_B;
#pragma unroll
        for (int i = 0; i < 4; i++) {
            const int idx = tid + i * 256;
            const int r = idx >> 3, c8 = (idx & 7) * 8;
            cp16(Abase + r * 144 + c8 * 2, Ab + (size_t)r * CC + k0 + c8);
            cp16(Bbase + r * 144 + c8 * 2, Bw + (size_t)r * CC + k0 + c8);
        }
    };

    const unsigned lrow = lane & 15, lchunk = (lane >> 4) * 16;
    const unsigned aoff = (wm * 64 + lrow) * 144 + lchunk;
    const unsigned boff = H_TILE_B + (wn * 32 + lrow) * 144 + lchunk;

    float c[4][4][4] = {};
    fill(0, 0); CP_COMMIT();
    fill(1, 1); CP_COMMIT();
    for (int kt = 0; kt < 16; kt++) {
        const int st = kt % NSTAGE;
        CP_WAIT1();
        __syncthreads();
        if (kt + 2 < 16) fill(kt + 2, (kt + 2) % NSTAGE);
        CP_COMMIT();
        mma_tile_f16(base + st * H_STAGE_B + aoff, base + st * H_STAGE_B + boff, c);
    }

    const int g = lane >> 2, t = lane & 3;
    const bool isq = (bc < 8);
    __half* rdst = isq ? g_qrh : g_krh;
#pragma unroll
    for (int nt = 0; nt < 4; nt++) {
        const int col = bc * 128 + wn * 32 + nt * 8 + 2 * t;
        const float b0 = bias[col], b1 = bias[col + 1];
        const int kp = (isq ? col : col - 1024) >> 1;
        const float theta = g_theta[kp];
#pragma unroll
        for (int mt = 0; mt < 4; mt++) {
#pragma unroll
            for (int e = 0; e < 2; e++) {
                const int row = br * 128 + wm * 64 + mt * 16 + g + e * 8;
                float v0 = c[mt][nt][2 * e]     + b0;
                float v1 = c[mt][nt][2 * e + 1] + b1;
                v0 = (v0 > 0.0f) ? (v0 + 1.0f) : expf(v0);
                v1 = (v1 > 0.0f) ? (v1 + 1.0f) : expf(v1);
                *(float2*)(g_qk + (size_t)row * 2048 + col) = make_float2(v0, v1);
                const int n = row & (NN - 1);
                float s, cw;
                sincosf((float)n * theta, &s, &cw);
                rdst[(size_t)row * 1024 + kp]       = __float2half_rn(cw * v0 - s * v1);
                rdst[(size_t)row * 1024 + 512 + kp] = __float2half_rn(cw * v1 + s * v0);
            }
        }
    }
}

// ---------------- lepe conv GEMM (fp16) -> g_lepeh ----------------
__global__ void __launch_bounds__(256, 2)
lepe_f16()
{
    extern __shared__ __align__(16) char dsm[];
    const unsigned base = sptr(dsm);
    const int tid = threadIdx.x, lane = tid & 31, wid = tid >> 5;
    const int wm = wid >> 2, wn = wid & 3;
    const int br = blockIdx.y, bc = blockIdx.x;
    const int m0 = br * 128;

    auto fill = [&](int kt, int st) {
        const int tap = kt >> 4;
        const int k0 = (kt & 15) * 64;
        const __half* Bw = g_lepewTh + (size_t)tap * CC * CC + (size_t)bc * 128 * CC;
        const unsigned Abase = base + st * H_STAGE_B;
        const unsigned Bbase = Abase + H_TILE_B;
#pragma unroll
        for (int i = 0; i < 4; i++) {
            const int idx = tid + i * 256;
            const int r = idx >> 3, c8 = (idx & 7) * 8;
            const int m = m0 + r;
            int n = (m & (NN - 1)) + tap - 1;
            const int b = m >> 12;
            const bool valid = (n >= 0) && (n < NN);
            if (!valid) n = 0;
            cp16z(Abase + r * 144 + c8 * 2,
                  g_xh + ((size_t)(b * NN + n)) * CC + k0 + c8, valid ? 16 : 0);
            cp16(Bbase + r * 144 + c8 * 2, Bw + (size_t)r * CC + k0 + c8);
        }
    };

    const unsigned lrow = lane & 15, lchunk = (lane >> 4) * 16;
    const unsigned aoff = (wm * 64 + lrow) * 144 + lchunk;
    const unsigned boff = H_TILE_B + (wn * 32 + lrow) * 144 + lchunk;

    float c[4][4][4] = {};
    fill(0, 0); CP_COMMIT();
    fill(1, 1); CP_COMMIT();
    for (int kt = 0; kt < 48; kt++) {
        const int st = kt % NSTAGE;
        CP_WAIT1();
        __syncthreads();
        if (kt + 2 < 48) fill(kt + 2, (kt + 2) % NSTAGE);
        CP_COMMIT();
        mma_tile_f16(base + st * H_STAGE_B + aoff, base + st * H_STAGE_B + boff, c);
    }

    const int g = lane >> 2, t = lane & 3;
#pragma unroll
    for (int mt = 0; mt < 4; mt++)
#pragma unroll
        for (int nt = 0; nt < 4; nt++) {
            const int col = bc * 128 + wn * 32 + nt * 8 + 2 * t;
#pragma unroll
            for (int e = 0; e < 2; e++) {
                const int row = m0 + wm * 64 + mt * 16 + g + e * 8;
                *(__half2*)(g_lepeh + (size_t)row * CC + col) =
                    __floats2half2_rn(c[mt][nt][2 * e], c[mt][nt][2 * e + 1]);
            }
        }
}

// ---------------- kv GEMM (fp16, trans-ldmatrix): kvT[e][d] ----------------
__global__ void __launch_bounds__(256, 2)
kv_f16()
{
    extern __shared__ __align__(16) char dsm[];
    const unsigned base = sptr(dsm);
    const int tid = threadIdx.x, lane = tid & 31, wid = tid >> 5;
    const int wm = wid >> 2, wn = wid & 3;
    const int chunk = blockIdx.x;
    const int bh = blockIdx.y;
    const int b = bh >> 3, h = bh & 7;
    const int n_base = chunk * (NN / KV_CHUNKS);
    const __half* Xs = g_xh  + ((size_t)b * NN) * CC + h * 128;
    const __half* Ks = g_krh + ((size_t)b * NN) * CC + h * 128;

    auto fill = [&](int kt, int st) {
        const int n0 = n_base + kt * 32;
        const unsigned Sbase = base + st * KVH_STAGE_B;
#pragma unroll
        for (int i = 0; i < 4; i++) {
            const int idx = tid + i * 256;
            const int tile = idx >> 9;
            const int j = idx & 511;
            const int r = j >> 4, ch = j & 15;
            const __half* src = (tile ? Ks : Xs) + (size_t)(n0 + r) * CC + ch * 8;
            cp16(Sbase + tile * KVH_TILE_B + r * 272 + ch * 16, src);
        }
    };

    const int L = lane;
    const unsigned a_row = (L & 7) + ((L >> 4) << 3);
    const unsigned a_colh = ((L >> 3) & 1) << 3;
    const unsigned b_row = (L & 7) + (((L >> 3) & 1) << 3);
    const unsigned b_colh = (L >> 4) << 3;

    float c[4][4][4] = {};
    fill(0, 0); CP_COMMIT();
    fill(1, 1); CP_COMMIT();
    const int NT = (NN / KV_CHUNKS) / 32;
    for (int kt = 0; kt < NT; kt++) {
        const int st = kt % NSTAGE;
        CP_WAIT1();
        __syncthreads();
        if (kt + 2 < NT) fill(kt + 2, (kt + 2) % NSTAGE);
        CP_COMMIT();
        const unsigned Xt = base + st * KVH_STAGE_B;
        const unsigned Kt = Xt + KVH_TILE_B;
#pragma unroll
        for (int ksi = 0; ksi < 2; ksi++) {
            const int k0 = ksi * 16;
            unsigned a[4][4], bb[2][4];
#pragma unroll
            for (int mt = 0; mt < 4; mt++)
                ldsm4t(a[mt], Xt + (k0 + a_row) * 272 + (wm * 64 + mt * 16 + a_colh) * 2);
#pragma unroll
            for (int ntp = 0; ntp < 2; ntp++)
                ldsm4t(bb[ntp], Kt + (k0 + b_row) * 272 + (wn * 32 + ntp * 16 + b_colh) * 2);
#pragma unroll
            for (int mt = 0; mt < 4; mt++)
#pragma unroll
                for (int ntp = 0; ntp < 2; ntp++) {
                    mma16(c[mt][2 * ntp],     a[mt][0], a[mt][1], a[mt][2], a[mt][3],
                          bb[ntp][0], bb[ntp][1]);
                    mma16(c[mt][2 * ntp + 1], a[mt][0], a[mt][1], a[mt][2], a[mt][3],
                          bb[ntp][2], bb[ntp][3]);
                }
        }
    }

    float* outp = g_kv_part + ((size_t)chunk * BB * HH + bh) * DD * DD;
    const int g = lane >> 2, t = lane & 3;
#pragma unroll
    for (int mt = 0; mt < 4; mt++)
#pragma unroll
        for (int nt = 0; nt < 4; nt++) {
            const int col = wn * 32 + nt * 8 + 2 * t;
#pragma unroll
            for (int e = 0; e < 2; e++) {
                const int row = wm * 64 + mt * 16 + g + e * 8;
                *(float2*)(outp + row * DD + col) =
                    make_float2(c[mt][nt][2 * e], c[mt][nt][2 * e + 1]);
            }
        }
}

__global__ void kv_reduce_kernel()
{
    const int i = blockIdx.x * 256 + threadIdx.x;
    if (i >= BB * HH * DD * DD) return;
    float s = 0.f;
    for (int ch = 0; ch < KV_CHUNKS; ch++)
        s += g_kv_part[(size_t)ch * BB * HH * DD * DD + i];
    g_kvTh[i] = __float2half_rn(s * (1.0f / 64.0f));
}

// ---------------- out = (qr @ kv) * z + lepe + lepe_b ----------------
__global__ void __launch_bounds__(256, 2)
out_f16(float* __restrict__ out, const float* __restrict__ lbias)
{
    extern __shared__ __align__(16) char dsm[];
    const unsigned base = sptr(dsm);
    const int tid = threadIdx.x, lane = tid & 31, wid = tid >> 5;
    const int wm = wid >> 2, wn = wid & 3;
    const int rt = blockIdx.x;
    const int bh = blockIdx.y;
    const int b = bh >> 3, h = bh & 7;
    const __half* Aq = g_qrh + (size_t)(b * NN + rt * 128) * CC + h * 128;
    const __half* Bk = g_kvTh + (size_t)bh * DD * DD;

    auto fill = [&](int kt, int st) {
        const int k0 = kt * 64;
        const unsigned Abase = base + st * H_STAGE_B;
        const unsigned Bbase = Abase + H_TILE_B;
#pragma unroll
        for (int i = 0; i < 4; i++) {
            const int idx = tid + i * 256;
            const int r = idx >> 3, c8 = (idx & 7) * 8;
            cp16(Abase + r * 144 + c8 * 2, Aq + (size_t)r * CC + k0 + c8);
            cp16(Bbase + r * 144 + c8 * 2, Bk + (size_t)r * DD + k0 + c8);
        }
    };

    const unsigned lrow = lane & 15, lchunk = (lane >> 4) * 16;
    const unsigned aoff = (wm * 64 + lrow) * 144 + lchunk;
    const unsigned boff = H_TILE_B + (wn * 32 + lrow) * 144 + lchunk;

    float c[4][4][4] = {};
    fill(0, 0); CP_COMMIT();
    fill(1, 1); CP_COMMIT();
    for (int kt = 0; kt < 2; kt++) {
        const int st = kt % NSTAGE;
        CP_WAIT1();
        __syncthreads();
        CP_COMMIT();
        mma_tile_f16(base + st * H_STAGE_B + aoff, base + st * H_STAGE_B + boff, c);
    }

    const int g = lane >> 2, t = lane & 3;
#pragma unroll
    for (int mt = 0; mt < 4; mt++)
#pragma unroll
        for (int e = 0; e < 2; e++) {
            const int n = rt * 128 + wm * 64 + mt * 16 + g + e * 8;
            const float zv = g_z[bh * NN + n];
            const size_t rowoff = ((size_t)(b * NN + n)) * CC + h * 128;
            float* orow = out + rowoff;
            const __half* lrow2 = g_lepeh + rowoff;
#pragma unroll
            for (int nt = 0; nt < 4; nt++) {
                const int col = wn * 32 + nt * 8 + 2 * t;
                const float2 lv = __half22float2(*(const __half2*)(lrow2 + col));
                const float lb0 = lbias[h * 128 + col];
                const float lb1 = lbias[h * 128 + col + 1];
                *(float2*)(orow + col) =
                    make_float2(c[mt][nt][2 * e] * zv + lv.x + lb0,
                                c[mt][nt][2 * e + 1] * zv + lv.y + lb1);
            }
        }
}

// ---------------- k mean / z ----------------
__global__ void kmean_part_kernel()
{
    const int chunk = blockIdx.x;
    const int b = blockIdx.y;
    const int c4 = threadIdx.x * 4;
    float4 s = make_float4(0.f, 0.f, 0.f, 0.f);
    for (int n = chunk * (NN / KM_CHUNKS); n < (chunk + 1) * (NN / KM_CHUNKS); n++) {
        const float4 v = *(const float4*)(g_qk + ((size_t)(b * NN + n)) * 2048 + 1024 + c4);
        s.x += v.x; s.y += v.y; s.z += v.z; s.w += v.w;
    }
    *(float4*)(&g_kmean_part[(chunk * BB + b) * CC + c4]) = s;
}

__global__ void kmean_fin_kernel()
{
    const int i = blockIdx.x * 256 + threadIdx.x;
    if (i >= BB * CC) return;
    float s = 0.f;
    for (int ch = 0; ch < KM_CHUNKS; ch++) s += g_kmean_part[ch * BB * CC + i];
    g_kmean[i] = s * (1.0f / NN);
}

__global__ void z_kernel()
{
    const int gw = (blockIdx.x * blockDim.x + threadIdx.x) >> 5;
    const int lane = threadIdx.x & 31;
    if (gw >= BB * HH * NN) return;
    const int n = gw & (NN - 1);
    const int h = (gw >> 12) & 7;
    const int b = gw >> 15;
    const float* qrow = g_qk + ((size_t)(b * NN + n)) * 2048 + h * 128;
    const float* km = g_kmean + b * CC + h * 128;
    const float4 qv = *(const float4*)(qrow + lane * 4);
    const float4 kv = *(const float4*)(km + lane * 4);
    float s = qv.x * kv.x + qv.y * kv.y + qv.z * kv.z + qv.w * kv.w;
#pragma unroll
    for (int o = 16; o; o >>= 1) s += __shfl_xor_sync(0xffffffffu, s, o);
    if (lane == 0) g_z[gw] = 1.0f / (s + 1e-6f);
}

// ---------------- launch ----------------
extern "C" void kernel_launch(void* const* d_in, const int* in_sizes, int n_in,
                              void* d_out, int out_size)
{
    const float* x      = (const float*)d_in[0];
    const float* qk_w   = (const float*)d_in[1];
    const float* qk_b   = (const float*)d_in[2];
    const float* lepe_w = (const float*)d_in[3];
    const float* lepe_b = (const float*)d_in[4];
    float* out = (float*)d_out;

    static cudaStream_t s1 = nullptr, s2 = nullptr;
    static cudaEvent_t evRoot = nullptr, evXh = nullptr, evQK = nullptr,
                       evZ = nullptr, evL = nullptr;
    static int init_done = 0;
    if (!init_done) {
        cudaFuncSetAttribute(gemm_qk_f16, cudaFuncAttributeMaxDynamicSharedMemorySize, H_DSMEM);
        cudaFuncSetAttribute(lepe_f16,    cudaFuncAttributeMaxDynamicSharedMemorySize, H_DSMEM);
        cudaFuncSetAttribute(kv_f16,      cudaFuncAttributeMaxDynamicSharedMemorySize, KVH_DSMEM);
        cudaFuncSetAttribute(out_f16,     cudaFuncAttributeMaxDynamicSharedMemorySize, H_DSMEM);
        cudaStreamCreateWithFlags(&s1, cudaStreamNonBlocking);
        cudaStreamCreateWithFlags(&s2, cudaStreamNonBlocking);
        cudaEventCreateWithFlags(&evRoot, cudaEventDisableTiming);
        cudaEventCreateWithFlags(&evXh, cudaEventDisableTiming);
        cudaEventCreateWithFlags(&evQK, cudaEventDisableTiming);
        cudaEventCreateWithFlags(&evZ, cudaEventDisableTiming);
        cudaEventCreateWithFlags(&evL, cudaEventDisableTiming);
        init_done = 1;
    }

    __half* d_xh;      cudaGetSymbolAddress((void**)&d_xh,      g_xh);
    __half* d_qkwTh;   cudaGetSymbolAddress((void**)&d_qkwTh,   g_qkwTh);
    __half* d_lepewTh; cudaGetSymbolAddress((void**)&d_lepewTh, g_lepewTh);

    cudaEventRecord(evRoot, 0);
    cudaStreamWaitEvent(s1, evRoot, 0);

    // s1: theta + lepe weight transpose, then lepe after x-half
    theta_init_kernel<<<1, 512, 0, s1>>>();
    transpose_cvt_h_kernel<<<dim3(32, 32, 3), dim3(32, 8), 0, s1>>>(lepe_w, d_lepewTh, CC, CC);

    // s0: fp16 x
    cvt_half_kernel<<<M_TOT * CC / 2048, 256>>>(x, d_xh);
    cudaEventRecord(evXh, 0);

    cudaStreamWaitEvent(s1, evXh, 0);
    lepe_f16<<<dim3(8, 128), 256, H_DSMEM, s1>>>();
    cudaEventRecord(evL, s1);

    // s0: attention chain
    transpose_cvt_h_kernel<<<dim3(64, 32, 1), dim3(32, 8)>>>(qk_w, d_qkwTh, CC, 2 * CC);
    gemm_qk_f16<<<dim3(16, 128), 256, H_DSMEM>>>(qk_b);
    cudaEventRecord(evQK, 0);

    // s2: kmean + z overlapping kv
    cudaStreamWaitEvent(s2, evQK, 0);
    kmean_part_kernel<<<dim3(KM_CHUNKS, BB), 256, 0, s2>>>();
    kmean_fin_kernel<<<16, 256, 0, s2>>>();
    z_kernel<<<(BB * HH * NN * 32) / 256, 256, 0, s2>>>();
    cudaEventRecord(evZ, s2);

    // s0: kv
    kv_f16<<<dim3(KV_CHUNKS, BB * HH), 256, KVH_DSMEM>>>();
    kv_reduce_kernel<<<(BB * HH * DD * DD) / 256, 256>>>();

    // join
    cudaStreamWaitEvent(0, evZ, 0);
    cudaStreamWaitEvent(0, evL, 0);
    out_f16<<<dim3(32, 32), 256, H_DSMEM>>>(out, lepe_b);
}

// round 13
// speedup vs baseline: 1.2373x; 1.0718x over previous
#include <cuda_runtime.h>
#include <cuda_fp16.h>
#include <math.h>

#define BB 4
#define NN 4096
#define CC 1024
#define HH 8
#define DD 128
#define M_TOT (BB*NN)      // 16384
#define KV_CHUNKS 8

// fp16 qk/lepe/out GEMM smem: two [128][64h +pad] tiles per stage, row=144B
#define H_TILE_B   (128 * 144)              // 18432
#define H_STAGE_B  (2 * H_TILE_B)           // 36864
#define NSTAGE     3
#define H_DSMEM    (NSTAGE * H_STAGE_B)     // 110592

// kv fp16 smem: two [32][128h] tiles, row = 272B
#define KVH_TILE_B  (32 * 272)
#define KVH_STAGE_B (2 * KVH_TILE_B)
#define KVH_DSMEM   (NSTAGE * KVH_STAGE_B)  // 52224

// ---------------- scratch ----------------
__device__ __half g_qh[(size_t)M_TOT * CC];          // elu+1 q (fp16, for z)
__device__ __half g_qrh[(size_t)M_TOT * CC];         // rope(q) fp16
__device__ __half g_krh[(size_t)M_TOT * CC];         // rope(k) fp16
__device__ __half g_lepeh[(size_t)M_TOT * CC];       // lepe fp16
__device__ float  g_kmean_part[128 * CC];            // per-row-chunk k column sums
__device__ float  g_kmean[BB * CC];
__device__ float  g_z[BB * HH * NN];
__device__ float  g_kv_part[(size_t)KV_CHUNKS * BB * HH * DD * DD];
__device__ __half g_kvTh[(size_t)BB * HH * DD * DD];
__device__ __half g_xh[(size_t)M_TOT * CC];
__device__ __half g_qkwTh[(size_t)2 * CC * CC];
__device__ __half g_lepewTh[(size_t)3 * CC * CC];
__device__ float  g_theta[512];

// ---------------- helpers ----------------
__device__ __forceinline__ unsigned sptr(const void* p)
{
    return (unsigned)__cvta_generic_to_shared(p);
}
__device__ __forceinline__ void cp16(unsigned dst, const void* src)
{
    asm volatile("cp.async.cg.shared.global [%0], [%1], 16;" :: "r"(dst), "l"(src));
}
__device__ __forceinline__ void cp16z(unsigned dst, const void* src, int sz)
{
    asm volatile("cp.async.cg.shared.global [%0], [%1], 16, %2;" :: "r"(dst), "l"(src), "r"(sz));
}
#define CP_COMMIT() asm volatile("cp.async.commit_group;" ::: "memory")
#define CP_WAIT1()  asm volatile("cp.async.wait_group 1;" ::: "memory")

__device__ __forceinline__ void mma16(float c[4], unsigned a0, unsigned a1, unsigned a2,
                                      unsigned a3, unsigned b0, unsigned b1)
{
    asm volatile(
        "mma.sync.aligned.m16n8k16.row.col.f32.f16.f16.f32 "
        "{%0,%1,%2,%3},{%4,%5,%6,%7},{%8,%9},{%0,%1,%2,%3};"
        : "+f"(c[0]), "+f"(c[1]), "+f"(c[2]), "+f"(c[3])
        : "r"(a0), "r"(a1), "r"(a2), "r"(a3), "r"(b0), "r"(b1));
}

__device__ __forceinline__ void ldsm4t(unsigned r[4], unsigned addr)
{
    asm volatile("ldmatrix.sync.aligned.m8n8.x4.trans.shared.b16 {%0,%1,%2,%3}, [%4];"
                 : "=r"(r[0]), "=r"(r[1]), "=r"(r[2]), "=r"(r[3]) : "r"(addr));
}

// ---------------- prepasses ----------------
__global__ void cvt_half_kernel(const float* __restrict__ src, __half* __restrict__ dst)
{
    const size_t i = ((size_t)blockIdx.x * blockDim.x + threadIdx.x) * 8;
    float4 v0 = *(const float4*)(src + i);
    float4 v1 = *(const float4*)(src + i + 4);
    __half2 h0 = __floats2half2_rn(v0.x, v0.y);
    __half2 h1 = __floats2half2_rn(v0.z, v0.w);
    __half2 h2 = __floats2half2_rn(v1.x, v1.y);
    __half2 h3 = __floats2half2_rn(v1.z, v1.w);
    uint4 u;
    u.x = *(unsigned*)&h0; u.y = *(unsigned*)&h1;
    u.z = *(unsigned*)&h2; u.w = *(unsigned*)&h3;
    *(uint4*)(dst + i) = u;
}

__global__ void transpose_cvt_h_kernel(const float* __restrict__ src, __half* __restrict__ dst,
                                       int R, int C)
{
    __shared__ float t[32][33];
    const size_t plane = (size_t)blockIdx.z * R * C;
    const float* s = src + plane;
    __half* d = dst + plane;
    const int x = blockIdx.x * 32 + threadIdx.x;
    const int y0 = blockIdx.y * 32 + threadIdx.y;
#pragma unroll
    for (int j = 0; j < 32; j += 8)
        t[threadIdx.y + j][threadIdx.x] = s[(size_t)(y0 + j) * C + x];
    __syncthreads();
    const int ox = blockIdx.y * 32 + threadIdx.x;
    const int oy0 = blockIdx.x * 32 + threadIdx.y;
#pragma unroll
    for (int j = 0; j < 32; j += 8)
        d[(size_t)(oy0 + j) * R + ox] = __float2half_rn(t[threadIdx.x][threadIdx.y + j]);
}

__global__ void theta_init_kernel()
{
    const int k = threadIdx.x;
    g_theta[k] = (float)exp(-(double)k * (log(10000.0) / 512.0));
}

// ---------------- fp16 warp-tile MMA over K=64 tile (scalar LDS, proven R10 path) ----
__device__ __forceinline__ void mma_tile_f16(const char* A, const char* B, float c[4][4][4])
{
#pragma unroll
    for (int ksi = 0; ksi < 4; ksi++) {
        unsigned a[4][4], b[4][2];
#pragma unroll
        for (int mt = 0; mt < 4; mt++) {
            const char* pa = A + mt * (16 * 144) + ksi * 32;
            a[mt][0] = *(const unsigned*)(pa);
            a[mt][1] = *(const unsigned*)(pa + 8 * 144);
            a[mt][2] = *(const unsigned*)(pa + 16);
            a[mt][3] = *(const unsigned*)(pa + 8 * 144 + 16);
        }
#pragma unroll
        for (int nt = 0; nt < 4; nt++) {
            const char* pb = B + nt * (8 * 144) + ksi * 32;
            b[nt][0] = *(const unsigned*)(pb);
            b[nt][1] = *(const unsigned*)(pb + 16);
        }
#pragma unroll
        for (int mt = 0; mt < 4; mt++)
#pragma unroll
            for (int nt = 0; nt < 4; nt++)
                mma16(c[mt][nt], a[mt][0], a[mt][1], a[mt][2], a[mt][3],
                      b[nt][0], b[nt][1]);
    }
}

// ---------------- qk GEMM + fused bias/elu/rope + in-kernel kmean partials ----------------
__global__ void __launch_bounds__(256, 2)
gemm_qk_f16(const float* __restrict__ bias)
{
    extern __shared__ __align__(16) char dsm[];
    __shared__ float red[8][32];
    const unsigned base = sptr(dsm);
    const int tid = threadIdx.x, lane = tid & 31, wid = tid >> 5;
    const int wm = wid >> 2, wn = wid & 3;
    const int br = blockIdx.y, bc = blockIdx.x;
    const __half* Ab = g_xh + (size_t)br * 128 * CC;
    const __half* Bw = g_qkwTh + (size_t)bc * 128 * CC;

    auto fill = [&](int kt, int st) {
        const int k0 = kt * 64;
        const unsigned Abase = base + st * H_STAGE_B;
        const unsigned Bbase = Abase + H_TILE_B;
#pragma unroll
        for (int i = 0; i < 4; i++) {
            const int idx = tid + i * 256;
            const int r = idx >> 3, c8 = (idx & 7) * 8;
            cp16(Abase + r * 144 + c8 * 2, Ab + (size_t)r * CC + k0 + c8);
            cp16(Bbase + r * 144 + c8 * 2, Bw + (size_t)r * CC + k0 + c8);
        }
    };

    const int g = lane >> 2, q = lane & 3;
    const unsigned aoff = (wm * 64 + g) * 144 + q * 4;
    const unsigned boff = H_TILE_B + (wn * 32 + g) * 144 + q * 4;

    float c[4][4][4] = {};
    fill(0, 0); CP_COMMIT();
    fill(1, 1); CP_COMMIT();
    for (int kt = 0; kt < 16; kt++) {
        const int st = kt % NSTAGE;
        CP_WAIT1();
        __syncthreads();
        if (kt + 2 < 16) fill(kt + 2, (kt + 2) % NSTAGE);
        CP_COMMIT();
        mma_tile_f16(dsm + st * H_STAGE_B + aoff, dsm + st * H_STAGE_B + boff, c);
    }

    const int t = lane & 3;
    const bool isq = (bc < 8);
    __half* rdst = isq ? g_qrh : g_krh;
    float ks[4][2] = {};                      // k-column partial sums (per nt, per pair elem)
#pragma unroll
    for (int nt = 0; nt < 4; nt++) {
        const int col = bc * 128 + wn * 32 + nt * 8 + 2 * t;
        const float b0 = bias[col], b1 = bias[col + 1];
        const int kp = (isq ? col : col - 1024) >> 1;
        const float theta = g_theta[kp];
#pragma unroll
        for (int mt = 0; mt < 4; mt++) {
#pragma unroll
            for (int e = 0; e < 2; e++) {
                const int row = br * 128 + wm * 64 + mt * 16 + g + e * 8;
                float v0 = c[mt][nt][2 * e]     + b0;
                float v1 = c[mt][nt][2 * e + 1] + b1;
                v0 = (v0 > 0.0f) ? (v0 + 1.0f) : expf(v0);
                v1 = (v1 > 0.0f) ? (v1 + 1.0f) : expf(v1);
                if (isq) {
                    *(__half2*)(g_qh + (size_t)row * 1024 + col) = __floats2half2_rn(v0, v1);
                } else {
                    ks[nt][0] += v0;
                    ks[nt][1] += v1;
                }
                const int n = row & (NN - 1);
                float s, cw;
                sincosf((float)n * theta, &s, &cw);
                rdst[(size_t)row * 1024 + kp]       = __float2half_rn(cw * v0 - s * v1);
                rdst[(size_t)row * 1024 + 512 + kp] = __float2half_rn(cw * v1 + s * v0);
            }
        }
    }

    if (!isq) {
        // reduce over g lanes (strides 4,8,16 within warp)
#pragma unroll
        for (int o = 4; o <= 16; o <<= 1)
#pragma unroll
            for (int nt = 0; nt < 4; nt++) {
                ks[nt][0] += __shfl_xor_sync(0xffffffffu, ks[nt][0], o);
                ks[nt][1] += __shfl_xor_sync(0xffffffffu, ks[nt][1], o);
            }
        if (g == 0) {
#pragma unroll
            for (int nt = 0; nt < 4; nt++) {
                red[wid][nt * 8 + 2 * t]     = ks[nt][0];
                red[wid][nt * 8 + 2 * t + 1] = ks[nt][1];
            }
        }
        __syncthreads();
        if (tid < 128) {
            const int cw = tid >> 5;       // wn
            const int r = tid & 31;        // nt*8 + 2t + j
            const float s = red[cw][r] + red[4 + cw][r];   // wm0 + wm1
            g_kmean_part[(size_t)br * 1024 + (bc - 8) * 128 + tid] = s;
        }
    }
}

__global__ void kmean_fin_kernel()
{
    const int i = blockIdx.x * 256 + threadIdx.x;   // BB*CC = 4096
    if (i >= BB * CC) return;
    const int b = i >> 10, col = i & 1023;
    float s = 0.f;
#pragma unroll
    for (int j = 0; j < 32; j++)
        s += g_kmean_part[(size_t)((b << 5) + j) * 1024 + col];
    g_kmean[i] = s * (1.0f / NN);
}

// ---------------- z = 1 / (q . k_mean + 1e-6), q in fp16 ----------------
__global__ void z_kernel()
{
    const int gw = (blockIdx.x * blockDim.x + threadIdx.x) >> 5;
    const int lane = threadIdx.x & 31;
    if (gw >= BB * HH * NN) return;
    const int n = gw & (NN - 1);
    const int h = (gw >> 12) & 7;
    const int b = gw >> 15;
    const __half* qrow = g_qh + ((size_t)(b * NN + n)) * 1024 + h * 128;
    const float* km = g_kmean + b * CC + h * 128;
    const __half2 q01 = *(const __half2*)(qrow + lane * 4);
    const __half2 q23 = *(const __half2*)(qrow + lane * 4 + 2);
    const float4 kv = *(const float4*)(km + lane * 4);
    const float2 f01 = __half22float2(q01);
    const float2 f23 = __half22float2(q23);
    float s = f01.x * kv.x + f01.y * kv.y + f23.x * kv.z + f23.y * kv.w;
#pragma unroll
    for (int o = 16; o; o >>= 1) s += __shfl_xor_sync(0xffffffffu, s, o);
    if (lane == 0) g_z[gw] = 1.0f / (s + 1e-6f);
}

// ---------------- lepe conv GEMM (fp16) -> g_lepeh ----------------
__global__ void __launch_bounds__(256, 2)
lepe_f16()
{
    extern __shared__ __align__(16) char dsm[];
    const unsigned base = sptr(dsm);
    const int tid = threadIdx.x, lane = tid & 31, wid = tid >> 5;
    const int wm = wid >> 2, wn = wid & 3;
    const int br = blockIdx.y, bc = blockIdx.x;
    const int m0 = br * 128;

    auto fill = [&](int kt, int st) {
        const int tap = kt >> 4;
        const int k0 = (kt & 15) * 64;
        const __half* Bw = g_lepewTh + (size_t)tap * CC * CC + (size_t)bc * 128 * CC;
        const unsigned Abase = base + st * H_STAGE_B;
        const unsigned Bbase = Abase + H_TILE_B;
#pragma unroll
        for (int i = 0; i < 4; i++) {
            const int idx = tid + i * 256;
            const int r = idx >> 3, c8 = (idx & 7) * 8;
            const int m = m0 + r;
            int n = (m & (NN - 1)) + tap - 1;
            const int b = m >> 12;
            const bool valid = (n >= 0) && (n < NN);
            if (!valid) n = 0;
            cp16z(Abase + r * 144 + c8 * 2,
                  g_xh + ((size_t)(b * NN + n)) * CC + k0 + c8, valid ? 16 : 0);
            cp16(Bbase + r * 144 + c8 * 2, Bw + (size_t)r * CC + k0 + c8);
        }
    };

    const int g = lane >> 2, q = lane & 3;
    const unsigned aoff = (wm * 64 + g) * 144 + q * 4;
    const unsigned boff = H_TILE_B + (wn * 32 + g) * 144 + q * 4;

    float c[4][4][4] = {};
    fill(0, 0); CP_COMMIT();
    fill(1, 1); CP_COMMIT();
    for (int kt = 0; kt < 48; kt++) {
        const int st = kt % NSTAGE;
        CP_WAIT1();
        __syncthreads();
        if (kt + 2 < 48) fill(kt + 2, (kt + 2) % NSTAGE);
        CP_COMMIT();
        mma_tile_f16(dsm + st * H_STAGE_B + aoff, dsm + st * H_STAGE_B + boff, c);
    }

    const int t = lane & 3;
#pragma unroll
    for (int mt = 0; mt < 4; mt++)
#pragma unroll
        for (int nt = 0; nt < 4; nt++) {
            const int col = bc * 128 + wn * 32 + nt * 8 + 2 * t;
#pragma unroll
            for (int e = 0; e < 2; e++) {
                const int row = m0 + wm * 64 + mt * 16 + g + e * 8;
                *(__half2*)(g_lepeh + (size_t)row * CC + col) =
                    __floats2half2_rn(c[mt][nt][2 * e], c[mt][nt][2 * e + 1]);
            }
        }
}

// ---------------- kv GEMM (fp16, trans-ldmatrix): kvT[e][d] ----------------
__global__ void __launch_bounds__(256, 2)
kv_f16()
{
    extern __shared__ __align__(16) char dsm[];
    const unsigned base = sptr(dsm);
    const int tid = threadIdx.x, lane = tid & 31, wid = tid >> 5;
    const int wm = wid >> 2, wn = wid & 3;
    const int chunk = blockIdx.x;
    const int bh = blockIdx.y;
    const int b = bh >> 3, h = bh & 7;
    const int n_base = chunk * (NN / KV_CHUNKS);
    const __half* Xs = g_xh  + ((size_t)b * NN) * CC + h * 128;
    const __half* Ks = g_krh + ((size_t)b * NN) * CC + h * 128;

    auto fill = [&](int kt, int st) {
        const int n0 = n_base + kt * 32;
        const unsigned Sbase = base + st * KVH_STAGE_B;
#pragma unroll
        for (int i = 0; i < 4; i++) {
            const int idx = tid + i * 256;
            const int tile = idx >> 9;
            const int j = idx & 511;
            const int r = j >> 4, ch = j & 15;
            const __half* src = (tile ? Ks : Xs) + (size_t)(n0 + r) * CC + ch * 8;
            cp16(Sbase + tile * KVH_TILE_B + r * 272 + ch * 16, src);
        }
    };

    const int L = lane;
    const unsigned a_row = (L & 7) + ((L >> 4) << 3);
    const unsigned a_colh = ((L >> 3) & 1) << 3;
    const unsigned b_row = (L & 7) + (((L >> 3) & 1) << 3);
    const unsigned b_colh = (L >> 4) << 3;

    float c[4][4][4] = {};
    fill(0, 0); CP_COMMIT();
    fill(1, 1); CP_COMMIT();
    const int NT = (NN / KV_CHUNKS) / 32;
    for (int kt = 0; kt < NT; kt++) {
        const int st = kt % NSTAGE;
        CP_WAIT1();
        __syncthreads();
        if (kt + 2 < NT) fill(kt + 2, (kt + 2) % NSTAGE);
        CP_COMMIT();
        const unsigned Xt = base + st * KVH_STAGE_B;
        const unsigned Kt = Xt + KVH_TILE_B;
#pragma unroll
        for (int ksi = 0; ksi < 2; ksi++) {
            const int k0 = ksi * 16;
            unsigned a[4][4], bb[2][4];
#pragma unroll
            for (int mt = 0; mt < 4; mt++)
                ldsm4t(a[mt], Xt + (k0 + a_row) * 272 + (wm * 64 + mt * 16 + a_colh) * 2);
#pragma unroll
            for (int ntp = 0; ntp < 2; ntp++)
                ldsm4t(bb[ntp], Kt + (k0 + b_row) * 272 + (wn * 32 + ntp * 16 + b_colh) * 2);
#pragma unroll
            for (int mt = 0; mt < 4; mt++)
#pragma unroll
                for (int ntp = 0; ntp < 2; ntp++) {
                    mma16(c[mt][2 * ntp],     a[mt][0], a[mt][1], a[mt][2], a[mt][3],
                          bb[ntp][0], bb[ntp][1]);
                    mma16(c[mt][2 * ntp + 1], a[mt][0], a[mt][1], a[mt][2], a[mt][3],
                          bb[ntp][2], bb[ntp][3]);
                }
        }
    }

    float* outp = g_kv_part + ((size_t)chunk * BB * HH + bh) * DD * DD;
    const int g = lane >> 2, t = lane & 3;
#pragma unroll
    for (int mt = 0; mt < 4; mt++)
#pragma unroll
        for (int nt = 0; nt < 4; nt++) {
            const int col = wn * 32 + nt * 8 + 2 * t;
#pragma unroll
            for (int e = 0; e < 2; e++) {
                const int row = wm * 64 + mt * 16 + g + e * 8;
                *(float2*)(outp + row * DD + col) =
                    make_float2(c[mt][nt][2 * e], c[mt][nt][2 * e + 1]);
            }
        }
}

__global__ void kv_reduce_kernel()
{
    const int i = blockIdx.x * 256 + threadIdx.x;
    if (i >= BB * HH * DD * DD) return;
    float s = 0.f;
    for (int ch = 0; ch < KV_CHUNKS; ch++)
        s += g_kv_part[(size_t)ch * BB * HH * DD * DD + i];
    g_kvTh[i] = __float2half_rn(s * (1.0f / 64.0f));
}

// ---------------- out = (qr @ kv) * z + lepe + lepe_b ----------------
__global__ void __launch_bounds__(256, 2)
out_f16(float* __restrict__ out, const float* __restrict__ lbias)
{
    extern __shared__ __align__(16) char dsm[];
    const unsigned base = sptr(dsm);
    const int tid = threadIdx.x, lane = tid & 31, wid = tid >> 5;
    const int wm = wid >> 2, wn = wid & 3;
    const int rt = blockIdx.x;
    const int bh = blockIdx.y;
    const int b = bh >> 3, h = bh & 7;
    const __half* Aq = g_qrh + (size_t)(b * NN + rt * 128) * CC + h * 128;
    const __half* Bk = g_kvTh + (size_t)bh * DD * DD;

    auto fill = [&](int kt, int st) {
        const int k0 = kt * 64;
        const unsigned Abase = base + st * H_STAGE_B;
        const unsigned Bbase = Abase + H_TILE_B;
#pragma unroll
        for (int i = 0; i < 4; i++) {
            const int idx = tid + i * 256;
            const int r = idx >> 3, c8 = (idx & 7) * 8;
            cp16(Abase + r * 144 + c8 * 2, Aq + (size_t)r * CC + k0 + c8);
            cp16(Bbase + r * 144 + c8 * 2, Bk + (size_t)r * DD + k0 + c8);
        }
    };

    const int g = lane >> 2, q = lane & 3;
    const unsigned aoff = (wm * 64 + g) * 144 + q * 4;
    const unsigned boff = H_TILE_B + (wn * 32 + g) * 144 + q * 4;

    float c[4][4][4] = {};
    fill(0, 0); CP_COMMIT();
    fill(1, 1); CP_COMMIT();
    for (int kt = 0; kt < 2; kt++) {
        const int st = kt % NSTAGE;
        CP_WAIT1();
        __syncthreads();
        CP_COMMIT();
        mma_tile_f16(dsm + st * H_STAGE_B + aoff, dsm + st * H_STAGE_B + boff, c);
    }

    const int t = lane & 3;
#pragma unroll
    for (int mt = 0; mt < 4; mt++)
#pragma unroll
        for (int e = 0; e < 2; e++) {
            const int n = rt * 128 + wm * 64 + mt * 16 + g + e * 8;
            const float zv = g_z[bh * NN + n];
            const size_t rowoff = ((size_t)(b * NN + n)) * CC + h * 128;
            float* orow = out + rowoff;
            const __half* lrow2 = g_lepeh + rowoff;
#pragma unroll
            for (int nt = 0; nt < 4; nt++) {
                const int col = wn * 32 + nt * 8 + 2 * t;
                const float2 lv = __half22float2(*(const __half2*)(lrow2 + col));
                const float lb0 = lbias[h * 128 + col];
                const float lb1 = lbias[h * 128 + col + 1];
                *(float2*)(orow + col) =
                    make_float2(c[mt][nt][2 * e] * zv + lv.x + lb0,
                                c[mt][nt][2 * e + 1] * zv + lv.y + lb1);
            }
        }
}

// ---------------- launch ----------------
extern "C" void kernel_launch(void* const* d_in, const int* in_sizes, int n_in,
                              void* d_out, int out_size)
{
    const float* x      = (const float*)d_in[0];
    const float* qk_w   = (const float*)d_in[1];
    const float* qk_b   = (const float*)d_in[2];
    const float* lepe_w = (const float*)d_in[3];
    const float* lepe_b = (const float*)d_in[4];
    float* out = (float*)d_out;

    static cudaStream_t s1 = nullptr, s2 = nullptr;
    static cudaEvent_t evRoot = nullptr, evXh = nullptr, evW = nullptr,
                       evQK = nullptr, evZ = nullptr, evL = nullptr;
    static int init_done = 0;
    if (!init_done) {
        cudaFuncSetAttribute(gemm_qk_f16, cudaFuncAttributeMaxDynamicSharedMemorySize, H_DSMEM);
        cudaFuncSetAttribute(lepe_f16,    cudaFuncAttributeMaxDynamicSharedMemorySize, H_DSMEM);
        cudaFuncSetAttribute(kv_f16,      cudaFuncAttributeMaxDynamicSharedMemorySize, KVH_DSMEM);
        cudaFuncSetAttribute(out_f16,     cudaFuncAttributeMaxDynamicSharedMemorySize, H_DSMEM);
        cudaStreamCreateWithFlags(&s1, cudaStreamNonBlocking);
        cudaStreamCreateWithFlags(&s2, cudaStreamNonBlocking);
        cudaEventCreateWithFlags(&evRoot, cudaEventDisableTiming);
        cudaEventCreateWithFlags(&evXh, cudaEventDisableTiming);
        cudaEventCreateWithFlags(&evW, cudaEventDisableTiming);
        cudaEventCreateWithFlags(&evQK, cudaEventDisableTiming);
        cudaEventCreateWithFlags(&evZ, cudaEventDisableTiming);
        cudaEventCreateWithFlags(&evL, cudaEventDisableTiming);
        init_done = 1;
    }

    __half* d_xh;      cudaGetSymbolAddress((void**)&d_xh,      g_xh);
    __half* d_qkwTh;   cudaGetSymbolAddress((void**)&d_qkwTh,   g_qkwTh);
    __half* d_lepewTh; cudaGetSymbolAddress((void**)&d_lepewTh, g_lepewTh);

    cudaEventRecord(evRoot, 0);
    cudaStreamWaitEvent(s1, evRoot, 0);
    cudaStreamWaitEvent(s2, evRoot, 0);

    // s1: theta + lepe weight transpose, then lepe after x-half
    theta_init_kernel<<<1, 512, 0, s1>>>();
    transpose_cvt_h_kernel<<<dim3(32, 32, 3), dim3(32, 8), 0, s1>>>(lepe_w, d_lepewTh, CC, CC);

    // s2: qk weight transpose (parallel with cvt_half)
    transpose_cvt_h_kernel<<<dim3(64, 32, 1), dim3(32, 8), 0, s2>>>(qk_w, d_qkwTh, CC, 2 * CC);
    cudaEventRecord(evW, s2);

    // s0: fp16 x
    cvt_half_kernel<<<M_TOT * CC / 2048, 256>>>(x, d_xh);
    cudaEventRecord(evXh, 0);

    cudaStreamWaitEvent(s1, evXh, 0);
    lepe_f16<<<dim3(8, 128), 256, H_DSMEM, s1>>>();
    cudaEventRecord(evL, s1);

    // s0: attention chain (qk waits on its weights)
    cudaStreamWaitEvent(0, evW, 0);
    gemm_qk_f16<<<dim3(16, 128), 256, H_DSMEM>>>(qk_b);
    cudaEventRecord(evQK, 0);

    // s2: kmean_fin + z overlapping kv
    cudaStreamWaitEvent(s2, evQK, 0);
    kmean_fin_kernel<<<16, 256, 0, s2>>>();
    z_kernel<<<(BB * HH * NN * 32) / 256, 256, 0, s2>>>();
    cudaEventRecord(evZ, s2);

    // s0: kv
    kv_f16<<<dim3(KV_CHUNKS, BB * HH), 256, KVH_DSMEM>>>();
    kv_reduce_kernel<<<(BB * HH * DD * DD) / 256, 256>>>();

    // join
    cudaStreamWaitEvent(0, evZ, 0);
    cudaStreamWaitEvent(0, evL, 0);
    out_f16<<<dim3(32, 32), 256, H_DSMEM>>>(out, lepe_b);
}

// round 14
// speedup vs baseline: 1.2456x; 1.0067x over previous
#include <cuda_runtime.h>
#include <cuda_fp16.h>
#include <math.h>

#define BB 4
#define NN 4096
#define CC 1024
#define HH 8
#define DD 128
#define M_TOT (BB*NN)      // 16384
#define KV_CHUNKS 4

// fp16 qk/lepe/out GEMM smem: two [128][64h +pad] tiles per stage, row=144B
#define H_TILE_B   (128 * 144)              // 18432
#define H_STAGE_B  (2 * H_TILE_B)           // 36864
#define NSTAGE     3
#define H_DSMEM    (NSTAGE * H_STAGE_B)     // 110592

// kv fp16 smem: two [32][128h] tiles, row = 272B
#define KVH_TILE_B  (32 * 272)
#define KVH_STAGE_B (2 * KVH_TILE_B)
#define KVH_DSMEM   (NSTAGE * KVH_STAGE_B)  // 52224

// ---------------- scratch ----------------
__device__ __half g_qh[(size_t)M_TOT * CC];          // elu+1 q (fp16, for z)
__device__ __half g_qrh[(size_t)M_TOT * CC];         // rope(q) fp16
__device__ __half g_krh[(size_t)M_TOT * CC];         // rope(k) fp16
__device__ __half g_lepeh[(size_t)M_TOT * CC];       // lepe fp16
__device__ float  g_kmean_part[128 * CC];            // per-row-chunk k column sums
__device__ float  g_kmean[BB * CC];
__device__ float  g_z[BB * HH * NN];
__device__ float  g_kv_part[(size_t)KV_CHUNKS * BB * HH * DD * DD];
__device__ __half g_kvTh[(size_t)BB * HH * DD * DD];
__device__ __half g_xh[(size_t)M_TOT * CC];
__device__ __half g_qkwTh[(size_t)2 * CC * CC];
__device__ __half g_lepewTh[(size_t)3 * CC * CC];
__device__ float  g_theta[512];

// ---------------- helpers ----------------
__device__ __forceinline__ unsigned sptr(const void* p)
{
    return (unsigned)__cvta_generic_to_shared(p);
}
__device__ __forceinline__ void cp16(unsigned dst, const void* src)
{
    asm volatile("cp.async.cg.shared.global [%0], [%1], 16;" :: "r"(dst), "l"(src));
}
__device__ __forceinline__ void cp16z(unsigned dst, const void* src, int sz)
{
    asm volatile("cp.async.cg.shared.global [%0], [%1], 16, %2;" :: "r"(dst), "l"(src), "r"(sz));
}
#define CP_COMMIT() asm volatile("cp.async.commit_group;" ::: "memory")
#define CP_WAIT1()  asm volatile("cp.async.wait_group 1;" ::: "memory")

__device__ __forceinline__ void mma16(float c[4], unsigned a0, unsigned a1, unsigned a2,
                                      unsigned a3, unsigned b0, unsigned b1)
{
    asm volatile(
        "mma.sync.aligned.m16n8k16.row.col.f32.f16.f16.f32 "
        "{%0,%1,%2,%3},{%4,%5,%6,%7},{%8,%9},{%0,%1,%2,%3};"
        : "+f"(c[0]), "+f"(c[1]), "+f"(c[2]), "+f"(c[3])
        : "r"(a0), "r"(a1), "r"(a2), "r"(a3), "r"(b0), "r"(b1));
}

__device__ __forceinline__ void ldsm4t(unsigned r[4], unsigned addr)
{
    asm volatile("ldmatrix.sync.aligned.m8n8.x4.trans.shared.b16 {%0,%1,%2,%3}, [%4];"
                 : "=r"(r[0]), "=r"(r[1]), "=r"(r[2]), "=r"(r[3]) : "r"(addr));
}

// ---------------- prepasses ----------------
__global__ void cvt_half_kernel(const float* __restrict__ src, __half* __restrict__ dst)
{
    const size_t i = ((size_t)blockIdx.x * blockDim.x + threadIdx.x) * 8;
    float4 v0 = *(const float4*)(src + i);
    float4 v1 = *(const float4*)(src + i + 4);
    __half2 h0 = __floats2half2_rn(v0.x, v0.y);
    __half2 h1 = __floats2half2_rn(v0.z, v0.w);
    __half2 h2 = __floats2half2_rn(v1.x, v1.y);
    __half2 h3 = __floats2half2_rn(v1.z, v1.w);
    uint4 u;
    u.x = *(unsigned*)&h0; u.y = *(unsigned*)&h1;
    u.z = *(unsigned*)&h2; u.w = *(unsigned*)&h3;
    *(uint4*)(dst + i) = u;
}

__global__ void transpose_cvt_h_kernel(const float* __restrict__ src, __half* __restrict__ dst,
                                       int R, int C)
{
    __shared__ float t[32][33];
    const size_t plane = (size_t)blockIdx.z * R * C;
    const float* s = src + plane;
    __half* d = dst + plane;
    const int x = blockIdx.x * 32 + threadIdx.x;
    const int y0 = blockIdx.y * 32 + threadIdx.y;
#pragma unroll
    for (int j = 0; j < 32; j += 8)
        t[threadIdx.y + j][threadIdx.x] = s[(size_t)(y0 + j) * C + x];
    __syncthreads();
    const int ox = blockIdx.y * 32 + threadIdx.x;
    const int oy0 = blockIdx.x * 32 + threadIdx.y;
#pragma unroll
    for (int j = 0; j < 32; j += 8)
        d[(size_t)(oy0 + j) * R + ox] = __float2half_rn(t[threadIdx.x][threadIdx.y + j]);
}

__global__ void theta_init_kernel()
{
    const int k = threadIdx.x;
    g_theta[k] = (float)exp(-(double)k * (log(10000.0) / 512.0));
}

// ---------------- fp16 warp-tile MMA over K=64 tile (scalar LDS, proven path) ----
__device__ __forceinline__ void mma_tile_f16(const char* A, const char* B, float c[4][4][4])
{
#pragma unroll
    for (int ksi = 0; ksi < 4; ksi++) {
        unsigned a[4][4], b[4][2];
#pragma unroll
        for (int mt = 0; mt < 4; mt++) {
            const char* pa = A + mt * (16 * 144) + ksi * 32;
            a[mt][0] = *(const unsigned*)(pa);
            a[mt][1] = *(const unsigned*)(pa + 8 * 144);
            a[mt][2] = *(const unsigned*)(pa + 16);
            a[mt][3] = *(const unsigned*)(pa + 8 * 144 + 16);
        }
#pragma unroll
        for (int nt = 0; nt < 4; nt++) {
            const char* pb = B + nt * (8 * 144) + ksi * 32;
            b[nt][0] = *(const unsigned*)(pb);
            b[nt][1] = *(const unsigned*)(pb + 16);
        }
#pragma unroll
        for (int mt = 0; mt < 4; mt++)
#pragma unroll
            for (int nt = 0; nt < 4; nt++)
                mma16(c[mt][nt], a[mt][0], a[mt][1], a[mt][2], a[mt][3],
                      b[nt][0], b[nt][1]);
    }
}

// ---------------- qk GEMM + fused bias/elu/rope(recurrence) + kmean partials ----------------
__global__ void __launch_bounds__(256, 2)
gemm_qk_f16(const float* __restrict__ bias)
{
    extern __shared__ __align__(16) char dsm[];
    __shared__ float red[8][32];
    const unsigned base = sptr(dsm);
    const int tid = threadIdx.x, lane = tid & 31, wid = tid >> 5;
    const int wm = wid >> 2, wn = wid & 3;
    const int br = blockIdx.y, bc = blockIdx.x;
    const __half* Ab = g_xh + (size_t)br * 128 * CC;
    const __half* Bw = g_qkwTh + (size_t)bc * 128 * CC;

    auto fill = [&](int kt, int st) {
        const int k0 = kt * 64;
        const unsigned Abase = base + st * H_STAGE_B;
        const unsigned Bbase = Abase + H_TILE_B;
#pragma unroll
        for (int i = 0; i < 4; i++) {
            const int idx = tid + i * 256;
            const int r = idx >> 3, c8 = (idx & 7) * 8;
            cp16(Abase + r * 144 + c8 * 2, Ab + (size_t)r * CC + k0 + c8);
            cp16(Bbase + r * 144 + c8 * 2, Bw + (size_t)r * CC + k0 + c8);
        }
    };

    const int g = lane >> 2, q = lane & 3;
    const unsigned aoff = (wm * 64 + g) * 144 + q * 4;
    const unsigned boff = H_TILE_B + (wn * 32 + g) * 144 + q * 4;

    float c[4][4][4] = {};
    fill(0, 0); CP_COMMIT();
    fill(1, 1); CP_COMMIT();
    for (int kt = 0; kt < 16; kt++) {
        const int st = kt % NSTAGE;
        CP_WAIT1();
        __syncthreads();
        if (kt + 2 < 16) fill(kt + 2, (kt + 2) % NSTAGE);
        CP_COMMIT();
        mma_tile_f16(dsm + st * H_STAGE_B + aoff, dsm + st * H_STAGE_B + boff, c);
    }

    const int t = lane & 3;
    const bool isq = (bc < 8);
    __half* rdst = isq ? g_qrh : g_krh;
    float ks[4][2] = {};
    const int n0 = (br * 128 + wm * 64 + g) & (NN - 1);   // rows stay in one batch block
#pragma unroll
    for (int nt = 0; nt < 4; nt++) {
        const int col = bc * 128 + wn * 32 + nt * 8 + 2 * t;
        const float b0 = bias[col], b1 = bias[col + 1];
        const int kp = (isq ? col : col - 1024) >> 1;
        const float theta = g_theta[kp];
        float s, cw, sd, cd;
        sincosf((float)n0 * theta, &s, &cw);
        sincosf(8.0f * theta, &sd, &cd);
#pragma unroll
        for (int j = 0; j < 8; j++) {          // j = mt*2 + e  (n = n0 + 8j)
            const int mt = j >> 1, e = j & 1;
            const int row = br * 128 + wm * 64 + mt * 16 + g + e * 8;
            float v0 = c[mt][nt][2 * e]     + b0;
            float v1 = c[mt][nt][2 * e + 1] + b1;
            v0 = (v0 > 0.0f) ? (v0 + 1.0f) : expf(v0);
            v1 = (v1 > 0.0f) ? (v1 + 1.0f) : expf(v1);
            if (isq) {
                *(__half2*)(g_qh + (size_t)row * 1024 + col) = __floats2half2_rn(v0, v1);
            } else {
                ks[nt][0] += v0;
                ks[nt][1] += v1;
            }
            rdst[(size_t)row * 1024 + kp]       = __float2half_rn(cw * v0 - s * v1);
            rdst[(size_t)row * 1024 + 512 + kp] = __float2half_rn(cw * v1 + s * v0);
            const float cn = cw * cd - s * sd;  // rotate by 8*theta
            s = s * cd + cw * sd;
            cw = cn;
        }
    }

    if (!isq) {
#pragma unroll
        for (int o = 4; o <= 16; o <<= 1)
#pragma unroll
            for (int nt = 0; nt < 4; nt++) {
                ks[nt][0] += __shfl_xor_sync(0xffffffffu, ks[nt][0], o);
                ks[nt][1] += __shfl_xor_sync(0xffffffffu, ks[nt][1], o);
            }
        if (g == 0) {
#pragma unroll
            for (int nt = 0; nt < 4; nt++) {
                red[wid][nt * 8 + 2 * t]     = ks[nt][0];
                red[wid][nt * 8 + 2 * t + 1] = ks[nt][1];
            }
        }
        __syncthreads();
        if (tid < 128) {
            const int cw2 = tid >> 5;
            const int r = tid & 31;
            const float s2 = red[cw2][r] + red[4 + cw2][r];
            g_kmean_part[(size_t)br * 1024 + (bc - 8) * 128 + tid] = s2;
        }
    }
}

__global__ void kmean_fin_kernel()
{
    const int i = blockIdx.x * 256 + threadIdx.x;
    if (i >= BB * CC) return;
    const int b = i >> 10, col = i & 1023;
    float s = 0.f;
#pragma unroll
    for (int j = 0; j < 32; j++)
        s += g_kmean_part[(size_t)((b << 5) + j) * 1024 + col];
    g_kmean[i] = s * (1.0f / NN);
}

// ---------------- z = 1 / (q . k_mean + 1e-6), q in fp16 ----------------
__global__ void z_kernel()
{
    const int gw = (blockIdx.x * blockDim.x + threadIdx.x) >> 5;
    const int lane = threadIdx.x & 31;
    if (gw >= BB * HH * NN) return;
    const int n = gw & (NN - 1);
    const int h = (gw >> 12) & 7;
    const int b = gw >> 15;
    const __half* qrow = g_qh + ((size_t)(b * NN + n)) * 1024 + h * 128;
    const float* km = g_kmean + b * CC + h * 128;
    const __half2 q01 = *(const __half2*)(qrow + lane * 4);
    const __half2 q23 = *(const __half2*)(qrow + lane * 4 + 2);
    const float4 kv = *(const float4*)(km + lane * 4);
    const float2 f01 = __half22float2(q01);
    const float2 f23 = __half22float2(q23);
    float s = f01.x * kv.x + f01.y * kv.y + f23.x * kv.z + f23.y * kv.w;
#pragma unroll
    for (int o = 16; o; o >>= 1) s += __shfl_xor_sync(0xffffffffu, s, o);
    if (lane == 0) g_z[gw] = 1.0f / (s + 1e-6f);
}

// ---------------- lepe conv GEMM (fp16) -> g_lepeh ----------------
__global__ void __launch_bounds__(256, 2)
lepe_f16()
{
    extern __shared__ __align__(16) char dsm[];
    const unsigned base = sptr(dsm);
    const int tid = threadIdx.x, lane = tid & 31, wid = tid >> 5;
    const int wm = wid >> 2, wn = wid & 3;
    const int br = blockIdx.y, bc = blockIdx.x;
    const int m0 = br * 128;

    auto fill = [&](int kt, int st) {
        const int tap = kt >> 4;
        const int k0 = (kt & 15) * 64;
        const __half* Bw = g_lepewTh + (size_t)tap * CC * CC + (size_t)bc * 128 * CC;
        const unsigned Abase = base + st * H_STAGE_B;
        const unsigned Bbase = Abase + H_TILE_B;
#pragma unroll
        for (int i = 0; i < 4; i++) {
            const int idx = tid + i * 256;
            const int r = idx >> 3, c8 = (idx & 7) * 8;
            const int m = m0 + r;
            int n = (m & (NN - 1)) + tap - 1;
            const int b = m >> 12;
            const bool valid = (n >= 0) && (n < NN);
            if (!valid) n = 0;
            cp16z(Abase + r * 144 + c8 * 2,
                  g_xh + ((size_t)(b * NN + n)) * CC + k0 + c8, valid ? 16 : 0);
            cp16(Bbase + r * 144 + c8 * 2, Bw + (size_t)r * CC + k0 + c8);
        }
    };

    const int g = lane >> 2, q = lane & 3;
    const unsigned aoff = (wm * 64 + g) * 144 + q * 4;
    const unsigned boff = H_TILE_B + (wn * 32 + g) * 144 + q * 4;

    float c[4][4][4] = {};
    fill(0, 0); CP_COMMIT();
    fill(1, 1); CP_COMMIT();
    for (int kt = 0; kt < 48; kt++) {
        const int st = kt % NSTAGE;
        CP_WAIT1();
        __syncthreads();
        if (kt + 2 < 48) fill(kt + 2, (kt + 2) % NSTAGE);
        CP_COMMIT();
        mma_tile_f16(dsm + st * H_STAGE_B + aoff, dsm + st * H_STAGE_B + boff, c);
    }

    const int t = lane & 3;
#pragma unroll
    for (int mt = 0; mt < 4; mt++)
#pragma unroll
        for (int nt = 0; nt < 4; nt++) {
            const int col = bc * 128 + wn * 32 + nt * 8 + 2 * t;
#pragma unroll
            for (int e = 0; e < 2; e++) {
                const int row = m0 + wm * 64 + mt * 16 + g + e * 8;
                *(__half2*)(g_lepeh + (size_t)row * CC + col) =
                    __floats2half2_rn(c[mt][nt][2 * e], c[mt][nt][2 * e + 1]);
            }
        }
}

// ---------------- kv GEMM (fp16, trans-ldmatrix): kvT[e][d] ----------------
__global__ void __launch_bounds__(256, 2)
kv_f16()
{
    extern __shared__ __align__(16) char dsm[];
    const unsigned base = sptr(dsm);
    const int tid = threadIdx.x, lane = tid & 31, wid = tid >> 5;
    const int wm = wid >> 2, wn = wid & 3;
    const int chunk = blockIdx.x;
    const int bh = blockIdx.y;
    const int b = bh >> 3, h = bh & 7;
    const int n_base = chunk * (NN / KV_CHUNKS);
    const __half* Xs = g_xh  + ((size_t)b * NN) * CC + h * 128;
    const __half* Ks = g_krh + ((size_t)b * NN) * CC + h * 128;

    auto fill = [&](int kt, int st) {
        const int n0 = n_base + kt * 32;
        const unsigned Sbase = base + st * KVH_STAGE_B;
#pragma unroll
        for (int i = 0; i < 4; i++) {
            const int idx = tid + i * 256;
            const int tile = idx >> 9;
            const int j = idx & 511;
            const int r = j >> 4, ch = j & 15;
            const __half* src = (tile ? Ks : Xs) + (size_t)(n0 + r) * CC + ch * 8;
            cp16(Sbase + tile * KVH_TILE_B + r * 272 + ch * 16, src);
        }
    };

    const int L = lane;
    const unsigned a_row = (L & 7) + ((L >> 4) << 3);
    const unsigned a_colh = ((L >> 3) & 1) << 3;
    const unsigned b_row = (L & 7) + (((L >> 3) & 1) << 3);
    const unsigned b_colh = (L >> 4) << 3;

    float c[4][4][4] = {};
    fill(0, 0); CP_COMMIT();
    fill(1, 1); CP_COMMIT();
    const int NT = (NN / KV_CHUNKS) / 32;   // 32
    for (int kt = 0; kt < NT; kt++) {
        const int st = kt % NSTAGE;
        CP_WAIT1();
        __syncthreads();
        if (kt + 2 < NT) fill(kt + 2, (kt + 2) % NSTAGE);
        CP_COMMIT();
        const unsigned Xt = base + st * KVH_STAGE_B;
        const unsigned Kt = Xt + KVH_TILE_B;
#pragma unroll
        for (int ksi = 0; ksi < 2; ksi++) {
            const int k0 = ksi * 16;
            unsigned a[4][4], bb[2][4];
#pragma unroll
            for (int mt = 0; mt < 4; mt++)
                ldsm4t(a[mt], Xt + (k0 + a_row) * 272 + (wm * 64 + mt * 16 + a_colh) * 2);
#pragma unroll
            for (int ntp = 0; ntp < 2; ntp++)
                ldsm4t(bb[ntp], Kt + (k0 + b_row) * 272 + (wn * 32 + ntp * 16 + b_colh) * 2);
#pragma unroll
            for (int mt = 0; mt < 4; mt++)
#pragma unroll
                for (int ntp = 0; ntp < 2; ntp++) {
                    mma16(c[mt][2 * ntp],     a[mt][0], a[mt][1], a[mt][2], a[mt][3],
                          bb[ntp][0], bb[ntp][1]);
                    mma16(c[mt][2 * ntp + 1], a[mt][0], a[mt][1], a[mt][2], a[mt][3],
                          bb[ntp][2], bb[ntp][3]);
                }
        }
    }

    float* outp = g_kv_part + ((size_t)chunk * BB * HH + bh) * DD * DD;
    const int g = lane >> 2, t = lane & 3;
#pragma unroll
    for (int mt = 0; mt < 4; mt++)
#pragma unroll
        for (int nt = 0; nt < 4; nt++) {
            const int col = wn * 32 + nt * 8 + 2 * t;
#pragma unroll
            for (int e = 0; e < 2; e++) {
                const int row = wm * 64 + mt * 16 + g + e * 8;
                *(float2*)(outp + row * DD + col) =
                    make_float2(c[mt][nt][2 * e], c[mt][nt][2 * e + 1]);
            }
        }
}

__global__ void kv_reduce_kernel()
{
    const int i = blockIdx.x * 256 + threadIdx.x;
    if (i >= BB * HH * DD * DD) return;
    float s = 0.f;
#pragma unroll
    for (int ch = 0; ch < KV_CHUNKS; ch++)
        s += g_kv_part[(size_t)ch * BB * HH * DD * DD + i];
    g_kvTh[i] = __float2half_rn(s * (1.0f / 64.0f));
}

// ---------------- out = (qr @ kv) * z + lepe + lepe_b ----------------
__global__ void __launch_bounds__(256, 2)
out_f16(float* __restrict__ out, const float* __restrict__ lbias)
{
    extern __shared__ __align__(16) char dsm[];
    const unsigned base = sptr(dsm);
    const int tid = threadIdx.x, lane = tid & 31, wid = tid >> 5;
    const int wm = wid >> 2, wn = wid & 3;
    const int rt = blockIdx.x;
    const int bh = blockIdx.y;
    const int b = bh >> 3, h = bh & 7;
    const __half* Aq = g_qrh + (size_t)(b * NN + rt * 128) * CC + h * 128;
    const __half* Bk = g_kvTh + (size_t)bh * DD * DD;

    auto fill = [&](int kt, int st) {
        const int k0 = kt * 64;
        const unsigned Abase = base + st * H_STAGE_B;
        const unsigned Bbase = Abase + H_TILE_B;
#pragma unroll
        for (int i = 0; i < 4; i++) {
            const int idx = tid + i * 256;
            const int r = idx >> 3, c8 = (idx & 7) * 8;
            cp16(Abase + r * 144 + c8 * 2, Aq + (size_t)r * CC + k0 + c8);
            cp16(Bbase + r * 144 + c8 * 2, Bk + (size_t)r * DD + k0 + c8);
        }
    };

    const int g = lane >> 2, q = lane & 3;
    const unsigned aoff = (wm * 64 + g) * 144 + q * 4;
    const unsigned boff = H_TILE_B + (wn * 32 + g) * 144 + q * 4;

    float c[4][4][4] = {};
    fill(0, 0); CP_COMMIT();
    fill(1, 1); CP_COMMIT();
    for (int kt = 0; kt < 2; kt++) {
        const int st = kt % NSTAGE;
        CP_WAIT1();
        __syncthreads();
        CP_COMMIT();
        mma_tile_f16(dsm + st * H_STAGE_B + aoff, dsm + st * H_STAGE_B + boff, c);
    }

    const int t = lane & 3;
#pragma unroll
    for (int mt = 0; mt < 4; mt++)
#pragma unroll
        for (int e = 0; e < 2; e++) {
            const int n = rt * 128 + wm * 64 + mt * 16 + g + e * 8;
            const float zv = g_z[bh * NN + n];
            const size_t rowoff = ((size_t)(b * NN + n)) * CC + h * 128;
            float* orow = out + rowoff;
            const __half* lrow2 = g_lepeh + rowoff;
#pragma unroll
            for (int nt = 0; nt < 4; nt++) {
                const int col = wn * 32 + nt * 8 + 2 * t;
                const float2 lv = __half22float2(*(const __half2*)(lrow2 + col));
                const float lb0 = lbias[h * 128 + col];
                const float lb1 = lbias[h * 128 + col + 1];
                *(float2*)(orow + col) =
                    make_float2(c[mt][nt][2 * e] * zv + lv.x + lb0,
                                c[mt][nt][2 * e + 1] * zv + lv.y + lb1);
            }
        }
}

// ---------------- launch ----------------
extern "C" void kernel_launch(void* const* d_in, const int* in_sizes, int n_in,
                              void* d_out, int out_size)
{
    const float* x      = (const float*)d_in[0];
    const float* qk_w   = (const float*)d_in[1];
    const float* qk_b   = (const float*)d_in[2];
    const float* lepe_w = (const float*)d_in[3];
    const float* lepe_b = (const float*)d_in[4];
    float* out = (float*)d_out;

    static cudaStream_t s1 = nullptr, s2 = nullptr;
    static cudaEvent_t evRoot = nullptr, evXh = nullptr, evW = nullptr,
                       evQK = nullptr, evZ = nullptr, evL = nullptr;
    static int init_done = 0;
    if (!init_done) {
        cudaFuncSetAttribute(gemm_qk_f16, cudaFuncAttributeMaxDynamicSharedMemorySize, H_DSMEM);
        cudaFuncSetAttribute(lepe_f16,    cudaFuncAttributeMaxDynamicSharedMemorySize, H_DSMEM);
        cudaFuncSetAttribute(kv_f16,      cudaFuncAttributeMaxDynamicSharedMemorySize, KVH_DSMEM);
        cudaFuncSetAttribute(out_f16,     cudaFuncAttributeMaxDynamicSharedMemorySize, H_DSMEM);
        cudaStreamCreateWithFlags(&s1, cudaStreamNonBlocking);
        cudaStreamCreateWithFlags(&s2, cudaStreamNonBlocking);
        cudaEventCreateWithFlags(&evRoot, cudaEventDisableTiming);
        cudaEventCreateWithFlags(&evXh, cudaEventDisableTiming);
        cudaEventCreateWithFlags(&evW, cudaEventDisableTiming);
        cudaEventCreateWithFlags(&evQK, cudaEventDisableTiming);
        cudaEventCreateWithFlags(&evZ, cudaEventDisableTiming);
        cudaEventCreateWithFlags(&evL, cudaEventDisableTiming);
        init_done = 1;
    }

    __half* d_xh;      cudaGetSymbolAddress((void**)&d_xh,      g_xh);
    __half* d_qkwTh;   cudaGetSymbolAddress((void**)&d_qkwTh,   g_qkwTh);
    __half* d_lepewTh; cudaGetSymbolAddress((void**)&d_lepewTh, g_lepewTh);

    cudaEventRecord(evRoot, 0);
    cudaStreamWaitEvent(s1, evRoot, 0);
    cudaStreamWaitEvent(s2, evRoot, 0);

    // s1: theta + lepe weight transpose, then lepe after x-half
    theta_init_kernel<<<1, 512, 0, s1>>>();
    transpose_cvt_h_kernel<<<dim3(32, 32, 3), dim3(32, 8), 0, s1>>>(lepe_w, d_lepewTh, CC, CC);

    // s2: qk weight transpose (parallel with cvt_half)
    transpose_cvt_h_kernel<<<dim3(64, 32, 1), dim3(32, 8), 0, s2>>>(qk_w, d_qkwTh, CC, 2 * CC);
    cudaEventRecord(evW, s2);

    // s0: fp16 x
    cvt_half_kernel<<<M_TOT * CC / 2048, 256>>>(x, d_xh);
    cudaEventRecord(evXh, 0);

    cudaStreamWaitEvent(s1, evXh, 0);
    lepe_f16<<<dim3(8, 128), 256, H_DSMEM, s1>>>();
    cudaEventRecord(evL, s1);

    // s0: attention chain (qk waits on its weights)
    cudaStreamWaitEvent(0, evW, 0);
    gemm_qk_f16<<<dim3(16, 128), 256, H_DSMEM>>>(qk_b);
    cudaEventRecord(evQK, 0);

    // s2: kmean_fin + z overlapping kv
    cudaStreamWaitEvent(s2, evQK, 0);
    kmean_fin_kernel<<<16, 256, 0, s2>>>();
    z_kernel<<<(BB * HH * NN * 32) / 256, 256, 0, s2>>>();
    cudaEventRecord(evZ, s2);

    // s0: kv
    kv_f16<<<dim3(KV_CHUNKS, BB * HH), 256, KVH_DSMEM>>>();
    kv_reduce_kernel<<<(BB * HH * DD * DD) / 256, 256>>>();

    // join
    cudaStreamWaitEvent(0, evZ, 0);
    cudaStreamWaitEvent(0, evL, 0);
    out_f16<<<dim3(32, 32), 256, H_DSMEM>>>(out, lepe_b);
}